// round 3
// baseline (speedup 1.0000x reference)
#include <cuda_runtime.h>
#include <cuda_bf16.h>
#include <math.h>

// Problem constants (fixed by the dataset)
#define MAXN 50000
#define MAXE 1600000

// ---------------- scratch (device globals; no allocation allowed) ----------
// Kernels reference these directly by symbol; host code never touches them.
__device__ __align__(16) float g_h[MAXN * 128];     // GEMM outputs (layer3 uses stride 64)
__device__ __align__(16) float g_a[MAXN * 128];     // aggregation outputs
__device__ __align__(16) float g_w3pad[128 * 64];   // zero-padded W3 (128x40 -> 128x64)
__device__ __align__(16) float g_dinv[MAXN];
__device__ int   g_cnt[MAXN];
__device__ int   g_rowptr[MAXN + 1];
__device__ int   g_cursor[MAXN];
__device__ int   g_srcidx[MAXE];

// ---------------- helpers ---------------------------------------------------
__device__ __forceinline__ float2 ffma2(float2 a, float2 b, float2 c) {
    unsigned long long A = *reinterpret_cast<unsigned long long*>(&a);
    unsigned long long B = *reinterpret_cast<unsigned long long*>(&b);
    unsigned long long C = *reinterpret_cast<unsigned long long*>(&c);
    unsigned long long D;
    asm("fma.rn.f32x2 %0, %1, %2, %3;" : "=l"(D) : "l"(A), "l"(B), "l"(C));
    return *reinterpret_cast<float2*>(&D);
}

// ---------------- graph preprocessing ---------------------------------------
__global__ void zero_cnt_kernel(int n) {
    int i = blockIdx.x * blockDim.x + threadIdx.x;
    if (i < n) g_cnt[i] = 0;
}

// edge_index is int32 (JAX downcasts int64 randint without x64 enabled)
__global__ void hist_kernel(const int* __restrict__ ei, int ne) {
    int e = blockIdx.x * blockDim.x + threadIdx.x;
    if (e < ne) {
        int d = ei[ne + e];
        atomicAdd(&g_cnt[d], 1);
    }
}

__global__ void dinv_kernel(int n) {
    int i = blockIdx.x * blockDim.x + threadIdx.x;
    if (i < n) g_dinv[i] = rsqrtf((float)(g_cnt[i] + 1));  // +1 self-loop
}

// single-block exclusive scan over g_cnt -> g_rowptr, g_cursor
__global__ void scan_kernel(int n) {
    __shared__ int sh[1024];
    const int T = 1024;
    int t = threadIdx.x;
    int chunk = (n + T - 1) / T;
    int beg = t * chunk;
    int end = min(beg + chunk, n);
    int s = 0;
    for (int i = beg; i < end; i++) s += g_cnt[i];
    sh[t] = s;
    __syncthreads();
    // Hillis-Steele inclusive scan
    for (int off = 1; off < T; off <<= 1) {
        int v = (t >= off) ? sh[t - off] : 0;
        __syncthreads();
        sh[t] += v;
        __syncthreads();
    }
    int run = (t == 0) ? 0 : sh[t - 1];
    for (int i = beg; i < end; i++) {
        g_rowptr[i] = run;
        g_cursor[i] = run;
        run += g_cnt[i];
    }
    if (t == T - 1) g_rowptr[n] = run;
}

__global__ void fill_kernel(const int* __restrict__ ei, int ne) {
    int e = blockIdx.x * blockDim.x + threadIdx.x;
    if (e < ne) {
        int s = ei[e];
        int d = ei[ne + e];
        int pos = atomicAdd(&g_cursor[d], 1);
        g_srcidx[pos] = s;
    }
}

__global__ void padw3_kernel(const float* __restrict__ W3) {
    int i = blockIdx.x * blockDim.x + threadIdx.x;
    if (i < 128 * 64) {
        int r = i >> 6, c = i & 63;
        g_w3pad[i] = (c < 40) ? W3[r * 40 + c] : 0.0f;
    }
}

// ---------------- GEMM: C = A[M x 128] @ B[128 x BN], C written to g_h ------
// A_INTERNAL: A = g_a (stride 128). B_INTERNAL: B = g_w3pad (stride ldb).
template <int BM, int BN, bool A_INTERNAL, bool B_INTERNAL>
__global__ void gemm_kernel(const float* __restrict__ Aext,
                            const float* __restrict__ Bext,
                            int M, int ldb, int ldc) {
    const float* __restrict__ A = A_INTERNAL ? (const float*)g_a : Aext;
    const float* __restrict__ B = B_INTERNAL ? (const float*)g_w3pad : Bext;
    float* __restrict__ C = g_h;

    constexpr int TX = BN / 8;    // thread col groups (8 cols each)
    constexpr int TY = 256 / TX;  // thread row groups (4 rows each)
    static_assert(TY * 4 == BM, "tile mismatch");
    __shared__ __align__(16) float As[16][BM + 4];
    __shared__ __align__(16) float Bs[16][BN];

    int tid = threadIdx.x;
    int tx = tid % TX;
    int ty = tid / TX;
    int rowBase = blockIdx.x * BM;

    float2 acc[4][4];
#pragma unroll
    for (int m = 0; m < 4; m++)
#pragma unroll
        for (int p = 0; p < 4; p++) acc[m][p] = make_float2(0.f, 0.f);

    for (int k0 = 0; k0 < 128; k0 += 16) {
        // load A tile (BM x 16), store transposed As[k][m]
        constexpr int AF4 = BM / 64;  // float4 loads per thread
#pragma unroll
        for (int i = 0; i < AF4; i++) {
            int idx = tid + i * 256;   // 0 .. BM*4-1
            int r = idx >> 2;
            int kq = idx & 3;
            float4 v = make_float4(0.f, 0.f, 0.f, 0.f);
            int grow = rowBase + r;
            if (grow < M) v = *(const float4*)&A[grow * 128 + k0 + kq * 4];
            As[kq * 4 + 0][r] = v.x;
            As[kq * 4 + 1][r] = v.y;
            As[kq * 4 + 2][r] = v.z;
            As[kq * 4 + 3][r] = v.w;
        }
        // load B tile (16 x BN)
        constexpr int BF4 = BN / 64;
#pragma unroll
        for (int i = 0; i < BF4; i++) {
            int idx = tid + i * 256;
            int r = idx / (BN / 4);
            int c4 = idx % (BN / 4);
            *(float4*)&Bs[r][c4 * 4] =
                *(const float4*)&B[(k0 + r) * ldb + c4 * 4];
        }
        __syncthreads();
#pragma unroll
        for (int kk = 0; kk < 16; kk++) {
            float4 av = *(const float4*)&As[kk][ty * 4];
            float4 b0 = *(const float4*)&Bs[kk][tx * 8];
            float4 b1 = *(const float4*)&Bs[kk][tx * 8 + 4];
            float2 bp[4] = {make_float2(b0.x, b0.y), make_float2(b0.z, b0.w),
                            make_float2(b1.x, b1.y), make_float2(b1.z, b1.w)};
            float am[4] = {av.x, av.y, av.z, av.w};
#pragma unroll
            for (int m = 0; m < 4; m++) {
                float2 a2 = make_float2(am[m], am[m]);
#pragma unroll
                for (int p = 0; p < 4; p++) acc[m][p] = ffma2(a2, bp[p], acc[m][p]);
            }
        }
        __syncthreads();
    }
#pragma unroll
    for (int m = 0; m < 4; m++) {
        int grow = rowBase + ty * 4 + m;
        if (grow < M) {
            float4 o0 = make_float4(acc[m][0].x, acc[m][0].y, acc[m][1].x, acc[m][1].y);
            float4 o1 = make_float4(acc[m][2].x, acc[m][2].y, acc[m][3].x, acc[m][3].y);
            *(float4*)&C[grow * ldc + tx * 8] = o0;
            *(float4*)&C[grow * ldc + tx * 8 + 4] = o1;
        }
    }
}

// ---------------- aggregation (F=128), warp per node ------------------------
// reads g_h (stride 128), writes g_a (stride 128)
__global__ void agg128_kernel(const float* __restrict__ bias, int n, int do_relu) {
    int gw = (blockIdx.x * blockDim.x + threadIdx.x) >> 5;
    if (gw >= n) return;
    int lane = threadIdx.x & 31;
    const float4* __restrict__ hv = (const float4*)g_h;

    float dd = g_dinv[gw];
    float ws = dd * dd;
    float4 v = hv[gw * 32 + lane];  // self-loop
    float4 acc = make_float4(v.x * ws, v.y * ws, v.z * ws, v.w * ws);

    int beg = g_rowptr[gw];
    int end = g_rowptr[gw + 1];
    int i = beg;
    for (; i + 3 < end; i += 4) {
        int s0 = g_srcidx[i], s1 = g_srcidx[i + 1], s2 = g_srcidx[i + 2], s3 = g_srcidx[i + 3];
        float n0 = g_dinv[s0] * dd, n1 = g_dinv[s1] * dd, n2 = g_dinv[s2] * dd, n3 = g_dinv[s3] * dd;
        float4 v0 = hv[s0 * 32 + lane];
        float4 v1 = hv[s1 * 32 + lane];
        float4 v2 = hv[s2 * 32 + lane];
        float4 v3 = hv[s3 * 32 + lane];
        acc.x += n0 * v0.x + n1 * v1.x + n2 * v2.x + n3 * v3.x;
        acc.y += n0 * v0.y + n1 * v1.y + n2 * v2.y + n3 * v3.y;
        acc.z += n0 * v0.z + n1 * v1.z + n2 * v2.z + n3 * v3.z;
        acc.w += n0 * v0.w + n1 * v1.w + n2 * v2.w + n3 * v3.w;
    }
    for (; i < end; i++) {
        int s = g_srcidx[i];
        float nw = g_dinv[s] * dd;
        float4 vv = hv[s * 32 + lane];
        acc.x += nw * vv.x;
        acc.y += nw * vv.y;
        acc.z += nw * vv.z;
        acc.w += nw * vv.w;
    }
    float4 b = ((const float4*)bias)[lane];
    acc.x += b.x; acc.y += b.y; acc.z += b.z; acc.w += b.w;
    if (do_relu) {
        acc.x = fmaxf(acc.x, 0.f);
        acc.y = fmaxf(acc.y, 0.f);
        acc.z = fmaxf(acc.z, 0.f);
        acc.w = fmaxf(acc.w, 0.f);
    }
    ((float4*)g_a)[gw * 32 + lane] = acc;
}

// ---------------- layer 3 aggregation (F=40, g_h stride 64) + log_softmax ---
__global__ void agg40_softmax_kernel(const float* __restrict__ b3,
                                     float* __restrict__ out, int n) {
    int gw = (blockIdx.x * blockDim.x + threadIdx.x) >> 5;
    if (gw >= n) return;
    int lane = threadIdx.x & 31;
    bool act = lane < 20;  // each active lane handles 2 of 40 features
    const float2* __restrict__ hv = (const float2*)g_h;  // row stride = 32 float2

    float dd = g_dinv[gw];
    float ws = dd * dd;
    float2 acc = make_float2(0.f, 0.f);
    if (act) {
        float2 v = hv[gw * 32 + lane];
        acc.x = v.x * ws;
        acc.y = v.y * ws;
    }
    int beg = g_rowptr[gw];
    int end = g_rowptr[gw + 1];
    int i = beg;
    for (; i + 1 < end; i += 2) {
        int s0 = g_srcidx[i], s1 = g_srcidx[i + 1];
        float n0 = g_dinv[s0] * dd, n1 = g_dinv[s1] * dd;
        if (act) {
            float2 v0 = hv[s0 * 32 + lane];
            float2 v1 = hv[s1 * 32 + lane];
            acc.x += n0 * v0.x + n1 * v1.x;
            acc.y += n0 * v0.y + n1 * v1.y;
        }
    }
    if (i < end) {
        int s = g_srcidx[i];
        float nw = g_dinv[s] * dd;
        if (act) {
            float2 v = hv[s * 32 + lane];
            acc.x += nw * v.x;
            acc.y += nw * v.y;
        }
    }
    if (act) {
        acc.x += b3[lane * 2];
        acc.y += b3[lane * 2 + 1];
    }
    // log_softmax over the 40 values held by this warp
    float m = act ? fmaxf(acc.x, acc.y) : -INFINITY;
#pragma unroll
    for (int off = 16; off > 0; off >>= 1) m = fmaxf(m, __shfl_xor_sync(0xFFFFFFFFu, m, off));
    float se = act ? (expf(acc.x - m) + expf(acc.y - m)) : 0.f;
#pragma unroll
    for (int off = 16; off > 0; off >>= 1) se += __shfl_xor_sync(0xFFFFFFFFu, se, off);
    float ls = m + logf(se);
    if (act) {
        out[gw * 40 + lane * 2 + 0] = acc.x - ls;
        out[gw * 40 + lane * 2 + 1] = acc.y - ls;
    }
}

// ---------------- launch -----------------------------------------------------
extern "C" void kernel_launch(void* const* d_in, const int* in_sizes, int n_in,
                              void* d_out, int out_size) {
    const float* x = (const float*)d_in[0];
    const int* ei = (const int*)d_in[1];     // edge_index stored as int32
    const float* W1 = (const float*)d_in[2];
    const float* b1 = (const float*)d_in[3];
    const float* W2 = (const float*)d_in[4];
    const float* b2 = (const float*)d_in[5];
    const float* W3 = (const float*)d_in[6];
    const float* b3 = (const float*)d_in[7];
    float* out = (float*)d_out;

    const int n = in_sizes[0] / 128;   // 50000 nodes
    const int ne = in_sizes[1] / 2;    // 1600000 edges

    int nb = (n + 255) / 256;
    int eb = (ne + 255) / 256;
    int wb = (n + 7) / 8;  // warp-per-node blocks of 256 threads

    // graph preprocessing (once per launch, reused by all 3 layers)
    zero_cnt_kernel<<<nb, 256>>>(n);
    hist_kernel<<<eb, 256>>>(ei, ne);
    dinv_kernel<<<nb, 256>>>(n);
    scan_kernel<<<1, 1024>>>(n);
    fill_kernel<<<eb, 256>>>(ei, ne);
    padw3_kernel<<<32, 256>>>(W3);

    // layer 1: h = x @ W1 ; a = Agg(h) + b1, relu
    gemm_kernel<64, 128, false, false><<<(n + 63) / 64, 256>>>(x, W1, n, 128, 128);
    agg128_kernel<<<wb, 256>>>(b1, n, 1);
    // layer 2: h = a @ W2 ; a = Agg(h) + b2, relu
    gemm_kernel<64, 128, true, false><<<(n + 63) / 64, 256>>>(nullptr, W2, n, 128, 128);
    agg128_kernel<<<wb, 256>>>(b2, n, 1);
    // layer 3: h = a @ W3pad (N padded 40 -> 64) ; out = log_softmax(Agg(h) + b3)
    gemm_kernel<128, 64, true, true><<<(n + 127) / 128, 256>>>(nullptr, nullptr, n, 64, 64);
    agg40_softmax_kernel<<<wb, 256>>>(b3, out, n);
}

// round 4
// speedup vs baseline: 1.1860x; 1.1860x over previous
#include <cuda_runtime.h>
#include <cuda_bf16.h>
#include <math.h>

// Problem constants (fixed by the dataset)
#define MAXN 50000
#define MAXE 1600000
#define SCAN_TILE 256
#define MAXB ((MAXN + SCAN_TILE - 1) / SCAN_TILE)

// ---------------- scratch (device globals; no allocation allowed) ----------
__device__ __align__(16) float g_h[MAXN * 128];     // GEMM outputs (layer3 uses stride 64)
__device__ __align__(16) float g_a[MAXN * 128];     // aggregation outputs
__device__ __align__(16) float g_w3pad[128 * 64];   // zero-padded W3 (128x40 -> 128x64)
__device__ __align__(16) float g_dinv[MAXN];
__device__ int   g_cnt[MAXN];
__device__ int   g_rowptr[MAXN + 1];
__device__ int   g_cursor[MAXN];
__device__ int   g_srcidx[MAXE];
__device__ int   g_bsum[MAXB];
__device__ int   g_boff[MAXB];

// ---------------- helpers ---------------------------------------------------
__device__ __forceinline__ float2 ffma2(float2 a, float2 b, float2 c) {
    unsigned long long A = *reinterpret_cast<unsigned long long*>(&a);
    unsigned long long B = *reinterpret_cast<unsigned long long*>(&b);
    unsigned long long C = *reinterpret_cast<unsigned long long*>(&c);
    unsigned long long D;
    asm("fma.rn.f32x2 %0, %1, %2, %3;" : "=l"(D) : "l"(A), "l"(B), "l"(C));
    return *reinterpret_cast<float2*>(&D);
}

// ---------------- graph preprocessing ---------------------------------------
__global__ void zero_cnt_kernel(int n) {
    int i = blockIdx.x * blockDim.x + threadIdx.x;
    if (i < n) g_cnt[i] = 0;
}

// edge_index is int32
__global__ void hist_kernel(const int* __restrict__ ei, int ne) {
    int e = blockIdx.x * blockDim.x + threadIdx.x;
    if (e < ne) {
        int d = ei[ne + e];
        atomicAdd(&g_cnt[d], 1);
    }
}

__global__ void dinv_kernel(int n) {
    int i = blockIdx.x * blockDim.x + threadIdx.x;
    if (i < n) g_dinv[i] = rsqrtf((float)(g_cnt[i] + 1));  // +1 self-loop
}

// ---- grid-wide exclusive scan over g_cnt: 3 small passes --------------------
// pass 1: per-block (256-wide tile) sums
__global__ void scan_pass1(int n) {
    __shared__ int sh[SCAN_TILE];
    int t = threadIdx.x;
    int i = blockIdx.x * SCAN_TILE + t;
    int v = (i < n) ? g_cnt[i] : 0;
    sh[t] = v;
    __syncthreads();
    for (int off = SCAN_TILE / 2; off > 0; off >>= 1) {
        if (t < off) sh[t] += sh[t + off];
        __syncthreads();
    }
    if (t == 0) g_bsum[blockIdx.x] = sh[0];
}

// pass 2: single block exclusive scan over nb (<=196) block sums
__global__ void scan_pass2(int nb, int n) {
    __shared__ int sh[SCAN_TILE];
    int t = threadIdx.x;
    int v = (t < nb) ? g_bsum[t] : 0;
    sh[t] = v;
    __syncthreads();
    for (int off = 1; off < SCAN_TILE; off <<= 1) {
        int u = (t >= off) ? sh[t - off] : 0;
        __syncthreads();
        sh[t] += u;
        __syncthreads();
    }
    if (t < nb) g_boff[t] = sh[t] - v;  // exclusive
    if (t == nb - 1) g_rowptr[n] = sh[t];  // total edge count
}

// pass 3: per-block exclusive scan of the tile + block offset -> rowptr/cursor
__global__ void scan_pass3(int n) {
    __shared__ int sh[SCAN_TILE];
    int t = threadIdx.x;
    int i = blockIdx.x * SCAN_TILE + t;
    int v = (i < n) ? g_cnt[i] : 0;
    sh[t] = v;
    __syncthreads();
    for (int off = 1; off < SCAN_TILE; off <<= 1) {
        int u = (t >= off) ? sh[t - off] : 0;
        __syncthreads();
        sh[t] += u;
        __syncthreads();
    }
    if (i < n) {
        int excl = g_boff[blockIdx.x] + sh[t] - v;
        g_rowptr[i] = excl;
        g_cursor[i] = excl;
    }
}

__global__ void fill_kernel(const int* __restrict__ ei, int ne) {
    int e = blockIdx.x * blockDim.x + threadIdx.x;
    if (e < ne) {
        int s = ei[e];
        int d = ei[ne + e];
        int pos = atomicAdd(&g_cursor[d], 1);
        g_srcidx[pos] = s;
    }
}

__global__ void padw3_kernel(const float* __restrict__ W3) {
    int i = blockIdx.x * blockDim.x + threadIdx.x;
    if (i < 128 * 64) {
        int r = i >> 6, c = i & 63;
        g_w3pad[i] = (c < 40) ? W3[r * 40 + c] : 0.0f;
    }
}

// ---------------- GEMM: C = A[M x 128] @ B[128 x BN], C written to g_h ------
template <int BM, int BN, bool A_INTERNAL, bool B_INTERNAL>
__global__ void gemm_kernel(const float* __restrict__ Aext,
                            const float* __restrict__ Bext,
                            int M, int ldb, int ldc) {
    const float* __restrict__ A = A_INTERNAL ? (const float*)g_a : Aext;
    const float* __restrict__ B = B_INTERNAL ? (const float*)g_w3pad : Bext;
    float* __restrict__ C = g_h;

    constexpr int TX = BN / 8;    // thread col groups (8 cols each)
    constexpr int TY = 256 / TX;  // thread row groups (4 rows each)
    static_assert(TY * 4 == BM, "tile mismatch");
    __shared__ __align__(16) float As[16][BM + 4];
    __shared__ __align__(16) float Bs[16][BN];

    int tid = threadIdx.x;
    int tx = tid % TX;
    int ty = tid / TX;
    int rowBase = blockIdx.x * BM;

    float2 acc[4][4];
#pragma unroll
    for (int m = 0; m < 4; m++)
#pragma unroll
        for (int p = 0; p < 4; p++) acc[m][p] = make_float2(0.f, 0.f);

    for (int k0 = 0; k0 < 128; k0 += 16) {
        constexpr int AF4 = BM / 64;
#pragma unroll
        for (int i = 0; i < AF4; i++) {
            int idx = tid + i * 256;
            int r = idx >> 2;
            int kq = idx & 3;
            float4 v = make_float4(0.f, 0.f, 0.f, 0.f);
            int grow = rowBase + r;
            if (grow < M) v = *(const float4*)&A[grow * 128 + k0 + kq * 4];
            As[kq * 4 + 0][r] = v.x;
            As[kq * 4 + 1][r] = v.y;
            As[kq * 4 + 2][r] = v.z;
            As[kq * 4 + 3][r] = v.w;
        }
        constexpr int BF4 = BN / 64;
#pragma unroll
        for (int i = 0; i < BF4; i++) {
            int idx = tid + i * 256;
            int r = idx / (BN / 4);
            int c4 = idx % (BN / 4);
            *(float4*)&Bs[r][c4 * 4] =
                *(const float4*)&B[(k0 + r) * ldb + c4 * 4];
        }
        __syncthreads();
#pragma unroll
        for (int kk = 0; kk < 16; kk++) {
            float4 av = *(const float4*)&As[kk][ty * 4];
            float4 b0 = *(const float4*)&Bs[kk][tx * 8];
            float4 b1 = *(const float4*)&Bs[kk][tx * 8 + 4];
            float2 bp[4] = {make_float2(b0.x, b0.y), make_float2(b0.z, b0.w),
                            make_float2(b1.x, b1.y), make_float2(b1.z, b1.w)};
            float am[4] = {av.x, av.y, av.z, av.w};
#pragma unroll
            for (int m = 0; m < 4; m++) {
                float2 a2 = make_float2(am[m], am[m]);
#pragma unroll
                for (int p = 0; p < 4; p++) acc[m][p] = ffma2(a2, bp[p], acc[m][p]);
            }
        }
        __syncthreads();
    }
#pragma unroll
    for (int m = 0; m < 4; m++) {
        int grow = rowBase + ty * 4 + m;
        if (grow < M) {
            float4 o0 = make_float4(acc[m][0].x, acc[m][0].y, acc[m][1].x, acc[m][1].y);
            float4 o1 = make_float4(acc[m][2].x, acc[m][2].y, acc[m][3].x, acc[m][3].y);
            *(float4*)&C[grow * ldc + tx * 8] = o0;
            *(float4*)&C[grow * ldc + tx * 8 + 4] = o1;
        }
    }
}

// ---------------- aggregation (F=128), warp per node ------------------------
__global__ void agg128_kernel(const float* __restrict__ bias, int n, int do_relu) {
    int gw = (blockIdx.x * blockDim.x + threadIdx.x) >> 5;
    if (gw >= n) return;
    int lane = threadIdx.x & 31;
    const float4* __restrict__ hv = (const float4*)g_h;

    float dd = g_dinv[gw];
    float ws = dd * dd;
    float4 v = hv[gw * 32 + lane];  // self-loop
    float4 acc = make_float4(v.x * ws, v.y * ws, v.z * ws, v.w * ws);

    int beg = g_rowptr[gw];
    int end = g_rowptr[gw + 1];
    int i = beg;
    for (; i + 3 < end; i += 4) {
        int s0 = g_srcidx[i], s1 = g_srcidx[i + 1], s2 = g_srcidx[i + 2], s3 = g_srcidx[i + 3];
        float n0 = g_dinv[s0] * dd, n1 = g_dinv[s1] * dd, n2 = g_dinv[s2] * dd, n3 = g_dinv[s3] * dd;
        float4 v0 = hv[s0 * 32 + lane];
        float4 v1 = hv[s1 * 32 + lane];
        float4 v2 = hv[s2 * 32 + lane];
        float4 v3 = hv[s3 * 32 + lane];
        acc.x += n0 * v0.x + n1 * v1.x + n2 * v2.x + n3 * v3.x;
        acc.y += n0 * v0.y + n1 * v1.y + n2 * v2.y + n3 * v3.y;
        acc.z += n0 * v0.z + n1 * v1.z + n2 * v2.z + n3 * v3.z;
        acc.w += n0 * v0.w + n1 * v1.w + n2 * v2.w + n3 * v3.w;
    }
    for (; i < end; i++) {
        int s = g_srcidx[i];
        float nw = g_dinv[s] * dd;
        float4 vv = hv[s * 32 + lane];
        acc.x += nw * vv.x;
        acc.y += nw * vv.y;
        acc.z += nw * vv.z;
        acc.w += nw * vv.w;
    }
    float4 b = ((const float4*)bias)[lane];
    acc.x += b.x; acc.y += b.y; acc.z += b.z; acc.w += b.w;
    if (do_relu) {
        acc.x = fmaxf(acc.x, 0.f);
        acc.y = fmaxf(acc.y, 0.f);
        acc.z = fmaxf(acc.z, 0.f);
        acc.w = fmaxf(acc.w, 0.f);
    }
    ((float4*)g_a)[gw * 32 + lane] = acc;
}

// ---------------- layer 3 aggregation (F=40, g_h stride 64) + log_softmax ---
__global__ void agg40_softmax_kernel(const float* __restrict__ b3,
                                     float* __restrict__ out, int n) {
    int gw = (blockIdx.x * blockDim.x + threadIdx.x) >> 5;
    if (gw >= n) return;
    int lane = threadIdx.x & 31;
    bool act = lane < 20;
    const float2* __restrict__ hv = (const float2*)g_h;  // row stride = 32 float2

    float dd = g_dinv[gw];
    float ws = dd * dd;
    float2 acc = make_float2(0.f, 0.f);
    if (act) {
        float2 v = hv[gw * 32 + lane];
        acc.x = v.x * ws;
        acc.y = v.y * ws;
    }
    int beg = g_rowptr[gw];
    int end = g_rowptr[gw + 1];
    int i = beg;
    for (; i + 1 < end; i += 2) {
        int s0 = g_srcidx[i], s1 = g_srcidx[i + 1];
        float n0 = g_dinv[s0] * dd, n1 = g_dinv[s1] * dd;
        if (act) {
            float2 v0 = hv[s0 * 32 + lane];
            float2 v1 = hv[s1 * 32 + lane];
            acc.x += n0 * v0.x + n1 * v1.x;
            acc.y += n0 * v0.y + n1 * v1.y;
        }
    }
    if (i < end) {
        int s = g_srcidx[i];
        float nw = g_dinv[s] * dd;
        if (act) {
            float2 v = hv[s * 32 + lane];
            acc.x += nw * v.x;
            acc.y += nw * v.y;
        }
    }
    if (act) {
        acc.x += b3[lane * 2];
        acc.y += b3[lane * 2 + 1];
    }
    float m = act ? fmaxf(acc.x, acc.y) : -INFINITY;
#pragma unroll
    for (int off = 16; off > 0; off >>= 1) m = fmaxf(m, __shfl_xor_sync(0xFFFFFFFFu, m, off));
    float se = act ? (expf(acc.x - m) + expf(acc.y - m)) : 0.f;
#pragma unroll
    for (int off = 16; off > 0; off >>= 1) se += __shfl_xor_sync(0xFFFFFFFFu, se, off);
    float ls = m + logf(se);
    if (act) {
        out[gw * 40 + lane * 2 + 0] = acc.x - ls;
        out[gw * 40 + lane * 2 + 1] = acc.y - ls;
    }
}

// ---------------- launch -----------------------------------------------------
extern "C" void kernel_launch(void* const* d_in, const int* in_sizes, int n_in,
                              void* d_out, int out_size) {
    const float* x = (const float*)d_in[0];
    const int* ei = (const int*)d_in[1];     // edge_index stored as int32
    const float* W1 = (const float*)d_in[2];
    const float* b1 = (const float*)d_in[3];
    const float* W2 = (const float*)d_in[4];
    const float* b2 = (const float*)d_in[5];
    const float* W3 = (const float*)d_in[6];
    const float* b3 = (const float*)d_in[7];
    float* out = (float*)d_out;

    const int n = in_sizes[0] / 128;   // 50000 nodes
    const int ne = in_sizes[1] / 2;    // 1600000 edges

    int nb = (n + 255) / 256;
    int eb = (ne + 255) / 256;
    int wb = (n + 7) / 8;
    int sb = (n + SCAN_TILE - 1) / SCAN_TILE;

    // graph preprocessing (once per launch, reused by all 3 layers)
    zero_cnt_kernel<<<nb, 256>>>(n);
    hist_kernel<<<eb, 256>>>(ei, ne);
    dinv_kernel<<<nb, 256>>>(n);
    scan_pass1<<<sb, SCAN_TILE>>>(n);
    scan_pass2<<<1, SCAN_TILE>>>(sb, n);
    scan_pass3<<<sb, SCAN_TILE>>>(n);
    fill_kernel<<<eb, 256>>>(ei, ne);
    padw3_kernel<<<32, 256>>>(W3);

    // layer 1
    gemm_kernel<64, 128, false, false><<<(n + 63) / 64, 256>>>(x, W1, n, 128, 128);
    agg128_kernel<<<wb, 256>>>(b1, n, 1);
    // layer 2
    gemm_kernel<64, 128, true, false><<<(n + 63) / 64, 256>>>(nullptr, W2, n, 128, 128);
    agg128_kernel<<<wb, 256>>>(b2, n, 1);
    // layer 3 (N padded 40 -> 64)
    gemm_kernel<128, 64, true, true><<<(n + 127) / 128, 256>>>(nullptr, nullptr, n, 64, 64);
    agg40_softmax_kernel<<<wb, 256>>>(b3, out, n);
}

// round 5
// speedup vs baseline: 1.2970x; 1.0936x over previous
#include <cuda_runtime.h>
#include <cuda_bf16.h>
#include <cuda_fp16.h>
#include <math.h>

// Problem constants (fixed by the dataset)
#define MAXN 50000
#define MAXE 1600000
#define SCAN_TILE 256
#define MAXB ((MAXN + SCAN_TILE - 1) / SCAN_TILE)

// ---------------- scratch (device globals; no allocation allowed) ----------
__device__ __align__(16) float  g_h[MAXN * 128];    // fp32 GEMM out (layer3, stride 64)
__device__ __align__(16) __half g_h16[MAXN * 128];  // fp16 GEMM out (layers 1-2)
__device__ __align__(16) float  g_a[MAXN * 128];    // aggregation outputs
__device__ __align__(16) float  g_w3pad[128 * 64];  // zero-padded W3 (128x40 -> 128x64)
__device__ __align__(16) float  g_dinv[MAXN];
__device__ int   g_cnt[MAXN];
__device__ int   g_rowptr[MAXN + 1];
__device__ int   g_cursor[MAXN];
__device__ int   g_srcidx[MAXE];
__device__ int   g_bsum[MAXB];
__device__ int   g_boff[MAXB];

// ---------------- helpers ---------------------------------------------------
__device__ __forceinline__ float2 ffma2(float2 a, float2 b, float2 c) {
    unsigned long long A = *reinterpret_cast<unsigned long long*>(&a);
    unsigned long long B = *reinterpret_cast<unsigned long long*>(&b);
    unsigned long long C = *reinterpret_cast<unsigned long long*>(&c);
    unsigned long long D;
    asm("fma.rn.f32x2 %0, %1, %2, %3;" : "=l"(D) : "l"(A), "l"(B), "l"(C));
    return *reinterpret_cast<float2*>(&D);
}

// ---------------- graph preprocessing ---------------------------------------
__global__ void zero_cnt_kernel(int n) {
    int i = blockIdx.x * blockDim.x + threadIdx.x;
    if (i < n) g_cnt[i] = 0;
}

__global__ void hist_kernel(const int* __restrict__ ei, int ne) {
    int e = blockIdx.x * blockDim.x + threadIdx.x;
    if (e < ne) {
        int d = ei[ne + e];
        atomicAdd(&g_cnt[d], 1);
    }
}

__global__ void dinv_kernel(int n) {
    int i = blockIdx.x * blockDim.x + threadIdx.x;
    if (i < n) g_dinv[i] = rsqrtf((float)(g_cnt[i] + 1));  // +1 self-loop
}

// ---- grid-wide exclusive scan over g_cnt: 3 small passes --------------------
__global__ void scan_pass1(int n) {
    __shared__ int sh[SCAN_TILE];
    int t = threadIdx.x;
    int i = blockIdx.x * SCAN_TILE + t;
    int v = (i < n) ? g_cnt[i] : 0;
    sh[t] = v;
    __syncthreads();
    for (int off = SCAN_TILE / 2; off > 0; off >>= 1) {
        if (t < off) sh[t] += sh[t + off];
        __syncthreads();
    }
    if (t == 0) g_bsum[blockIdx.x] = sh[0];
}

__global__ void scan_pass2(int nb, int n) {
    __shared__ int sh[SCAN_TILE];
    int t = threadIdx.x;
    int v = (t < nb) ? g_bsum[t] : 0;
    sh[t] = v;
    __syncthreads();
    for (int off = 1; off < SCAN_TILE; off <<= 1) {
        int u = (t >= off) ? sh[t - off] : 0;
        __syncthreads();
        sh[t] += u;
        __syncthreads();
    }
    if (t < nb) g_boff[t] = sh[t] - v;  // exclusive
    if (t == nb - 1) g_rowptr[n] = sh[t];
}

__global__ void scan_pass3(int n) {
    __shared__ int sh[SCAN_TILE];
    int t = threadIdx.x;
    int i = blockIdx.x * SCAN_TILE + t;
    int v = (i < n) ? g_cnt[i] : 0;
    sh[t] = v;
    __syncthreads();
    for (int off = 1; off < SCAN_TILE; off <<= 1) {
        int u = (t >= off) ? sh[t - off] : 0;
        __syncthreads();
        sh[t] += u;
        __syncthreads();
    }
    if (i < n) {
        int excl = g_boff[blockIdx.x] + sh[t] - v;
        g_rowptr[i] = excl;
        g_cursor[i] = excl;
    }
}

__global__ void fill_kernel(const int* __restrict__ ei, int ne) {
    int e = blockIdx.x * blockDim.x + threadIdx.x;
    if (e < ne) {
        int s = ei[e];
        int d = ei[ne + e];
        int pos = atomicAdd(&g_cursor[d], 1);
        g_srcidx[pos] = s;
    }
}

__global__ void padw3_kernel(const float* __restrict__ W3) {
    int i = blockIdx.x * blockDim.x + threadIdx.x;
    if (i < 128 * 64) {
        int r = i >> 6, c = i & 63;
        g_w3pad[i] = (c < 40) ? W3[r * 40 + c] : 0.0f;
    }
}

// ---------------- GEMM: C = A[M x 128] @ B[128 x BN] ------------------------
// OUT_HALF: write fp16 to g_h16 (layers 1-2); else fp32 to g_h (layer 3).
template <int BM, int BN, bool A_INTERNAL, bool B_INTERNAL, bool OUT_HALF>
__global__ void gemm_kernel(const float* __restrict__ Aext,
                            const float* __restrict__ Bext,
                            int M, int ldb, int ldc) {
    const float* __restrict__ A = A_INTERNAL ? (const float*)g_a : Aext;
    const float* __restrict__ B = B_INTERNAL ? (const float*)g_w3pad : Bext;

    constexpr int TX = BN / 8;    // thread col groups (8 cols each)
    constexpr int TY = 256 / TX;  // thread row groups (4 rows each)
    static_assert(TY * 4 == BM, "tile mismatch");
    __shared__ __align__(16) float As[16][BM + 4];
    __shared__ __align__(16) float Bs[16][BN];

    int tid = threadIdx.x;
    int tx = tid % TX;
    int ty = tid / TX;
    int rowBase = blockIdx.x * BM;

    float2 acc[4][4];
#pragma unroll
    for (int m = 0; m < 4; m++)
#pragma unroll
        for (int p = 0; p < 4; p++) acc[m][p] = make_float2(0.f, 0.f);

    for (int k0 = 0; k0 < 128; k0 += 16) {
        constexpr int AF4 = BM / 64;
#pragma unroll
        for (int i = 0; i < AF4; i++) {
            int idx = tid + i * 256;
            int r = idx >> 2;
            int kq = idx & 3;
            float4 v = make_float4(0.f, 0.f, 0.f, 0.f);
            int grow = rowBase + r;
            if (grow < M) v = *(const float4*)&A[grow * 128 + k0 + kq * 4];
            As[kq * 4 + 0][r] = v.x;
            As[kq * 4 + 1][r] = v.y;
            As[kq * 4 + 2][r] = v.z;
            As[kq * 4 + 3][r] = v.w;
        }
        constexpr int BF4 = BN / 64;
#pragma unroll
        for (int i = 0; i < BF4; i++) {
            int idx = tid + i * 256;
            int r = idx / (BN / 4);
            int c4 = idx % (BN / 4);
            *(float4*)&Bs[r][c4 * 4] =
                *(const float4*)&B[(k0 + r) * ldb + c4 * 4];
        }
        __syncthreads();
#pragma unroll
        for (int kk = 0; kk < 16; kk++) {
            float4 av = *(const float4*)&As[kk][ty * 4];
            float4 b0 = *(const float4*)&Bs[kk][tx * 8];
            float4 b1 = *(const float4*)&Bs[kk][tx * 8 + 4];
            float2 bp[4] = {make_float2(b0.x, b0.y), make_float2(b0.z, b0.w),
                            make_float2(b1.x, b1.y), make_float2(b1.z, b1.w)};
            float am[4] = {av.x, av.y, av.z, av.w};
#pragma unroll
            for (int m = 0; m < 4; m++) {
                float2 a2 = make_float2(am[m], am[m]);
#pragma unroll
                for (int p = 0; p < 4; p++) acc[m][p] = ffma2(a2, bp[p], acc[m][p]);
            }
        }
        __syncthreads();
    }
#pragma unroll
    for (int m = 0; m < 4; m++) {
        int grow = rowBase + ty * 4 + m;
        if (grow < M) {
            if (OUT_HALF) {
                __half2 hh[4];
#pragma unroll
                for (int p = 0; p < 4; p++) hh[p] = __float22half2_rn(acc[m][p]);
                *(uint4*)&g_h16[grow * ldc + tx * 8] = *(uint4*)hh;
            } else {
                float4 o0 = make_float4(acc[m][0].x, acc[m][0].y, acc[m][1].x, acc[m][1].y);
                float4 o1 = make_float4(acc[m][2].x, acc[m][2].y, acc[m][3].x, acc[m][3].y);
                *(float4*)&g_h[grow * ldc + tx * 8] = o0;
                *(float4*)&g_h[grow * ldc + tx * 8 + 4] = o1;
            }
        }
    }
}

// ---------------- aggregation (F=128, fp16 source), warp per node -----------
// reads g_h16 (stride 128 halfs), writes g_a (fp32, stride 128)
__device__ __forceinline__ float4 half4_to_float4(uint2 raw) {
    __half2 p0 = *reinterpret_cast<__half2*>(&raw.x);
    __half2 p1 = *reinterpret_cast<__half2*>(&raw.y);
    float2 f0 = __half22float2(p0);
    float2 f1 = __half22float2(p1);
    return make_float4(f0.x, f0.y, f1.x, f1.y);
}

__global__ void agg128_kernel(const float* __restrict__ bias, int n, int do_relu) {
    int gw = (blockIdx.x * blockDim.x + threadIdx.x) >> 5;
    if (gw >= n) return;
    int lane = threadIdx.x & 31;
    const uint2* __restrict__ hv = (const uint2*)g_h16;  // 4 halfs per lane

    float dd = g_dinv[gw];
    float ws = dd * dd;
    float4 v = half4_to_float4(hv[gw * 32 + lane]);  // self-loop
    float4 acc = make_float4(v.x * ws, v.y * ws, v.z * ws, v.w * ws);

    int beg = g_rowptr[gw];
    int end = g_rowptr[gw + 1];
    int i = beg;
    for (; i + 3 < end; i += 4) {
        int s0 = g_srcidx[i], s1 = g_srcidx[i + 1], s2 = g_srcidx[i + 2], s3 = g_srcidx[i + 3];
        float n0 = g_dinv[s0] * dd, n1 = g_dinv[s1] * dd, n2 = g_dinv[s2] * dd, n3 = g_dinv[s3] * dd;
        uint2 r0 = hv[s0 * 32 + lane];
        uint2 r1 = hv[s1 * 32 + lane];
        uint2 r2 = hv[s2 * 32 + lane];
        uint2 r3 = hv[s3 * 32 + lane];
        float4 v0 = half4_to_float4(r0);
        float4 v1 = half4_to_float4(r1);
        float4 v2 = half4_to_float4(r2);
        float4 v3 = half4_to_float4(r3);
        acc.x += n0 * v0.x + n1 * v1.x + n2 * v2.x + n3 * v3.x;
        acc.y += n0 * v0.y + n1 * v1.y + n2 * v2.y + n3 * v3.y;
        acc.z += n0 * v0.z + n1 * v1.z + n2 * v2.z + n3 * v3.z;
        acc.w += n0 * v0.w + n1 * v1.w + n2 * v2.w + n3 * v3.w;
    }
    for (; i < end; i++) {
        int s = g_srcidx[i];
        float nw = g_dinv[s] * dd;
        float4 vv = half4_to_float4(hv[s * 32 + lane]);
        acc.x += nw * vv.x;
        acc.y += nw * vv.y;
        acc.z += nw * vv.z;
        acc.w += nw * vv.w;
    }
    float4 b = ((const float4*)bias)[lane];
    acc.x += b.x; acc.y += b.y; acc.z += b.z; acc.w += b.w;
    if (do_relu) {
        acc.x = fmaxf(acc.x, 0.f);
        acc.y = fmaxf(acc.y, 0.f);
        acc.z = fmaxf(acc.z, 0.f);
        acc.w = fmaxf(acc.w, 0.f);
    }
    ((float4*)g_a)[gw * 32 + lane] = acc;
}

// ---------------- layer 3 aggregation (F=40, g_h fp32 stride 64) + softmax --
__global__ void agg40_softmax_kernel(const float* __restrict__ b3,
                                     float* __restrict__ out, int n) {
    int gw = (blockIdx.x * blockDim.x + threadIdx.x) >> 5;
    if (gw >= n) return;
    int lane = threadIdx.x & 31;
    bool act = lane < 20;
    const float2* __restrict__ hv = (const float2*)g_h;  // row stride = 32 float2

    float dd = g_dinv[gw];
    float ws = dd * dd;
    float2 acc = make_float2(0.f, 0.f);
    if (act) {
        float2 v = hv[gw * 32 + lane];
        acc.x = v.x * ws;
        acc.y = v.y * ws;
    }
    int beg = g_rowptr[gw];
    int end = g_rowptr[gw + 1];
    int i = beg;
    for (; i + 1 < end; i += 2) {
        int s0 = g_srcidx[i], s1 = g_srcidx[i + 1];
        float n0 = g_dinv[s0] * dd, n1 = g_dinv[s1] * dd;
        if (act) {
            float2 v0 = hv[s0 * 32 + lane];
            float2 v1 = hv[s1 * 32 + lane];
            acc.x += n0 * v0.x + n1 * v1.x;
            acc.y += n0 * v0.y + n1 * v1.y;
        }
    }
    if (i < end) {
        int s = g_srcidx[i];
        float nw = g_dinv[s] * dd;
        if (act) {
            float2 v = hv[s * 32 + lane];
            acc.x += nw * v.x;
            acc.y += nw * v.y;
        }
    }
    if (act) {
        acc.x += b3[lane * 2];
        acc.y += b3[lane * 2 + 1];
    }
    float m = act ? fmaxf(acc.x, acc.y) : -INFINITY;
#pragma unroll
    for (int off = 16; off > 0; off >>= 1) m = fmaxf(m, __shfl_xor_sync(0xFFFFFFFFu, m, off));
    float se = act ? (expf(acc.x - m) + expf(acc.y - m)) : 0.f;
#pragma unroll
    for (int off = 16; off > 0; off >>= 1) se += __shfl_xor_sync(0xFFFFFFFFu, se, off);
    float ls = m + logf(se);
    if (act) {
        out[gw * 40 + lane * 2 + 0] = acc.x - ls;
        out[gw * 40 + lane * 2 + 1] = acc.y - ls;
    }
}

// ---------------- launch -----------------------------------------------------
extern "C" void kernel_launch(void* const* d_in, const int* in_sizes, int n_in,
                              void* d_out, int out_size) {
    const float* x = (const float*)d_in[0];
    const int* ei = (const int*)d_in[1];     // edge_index stored as int32
    const float* W1 = (const float*)d_in[2];
    const float* b1 = (const float*)d_in[3];
    const float* W2 = (const float*)d_in[4];
    const float* b2 = (const float*)d_in[5];
    const float* W3 = (const float*)d_in[6];
    const float* b3 = (const float*)d_in[7];
    float* out = (float*)d_out;

    const int n = in_sizes[0] / 128;   // 50000 nodes
    const int ne = in_sizes[1] / 2;    // 1600000 edges

    int nb = (n + 255) / 256;
    int eb = (ne + 255) / 256;
    int wb = (n + 7) / 8;
    int sb = (n + SCAN_TILE - 1) / SCAN_TILE;

    // preprocessing + layer-1 GEMM placed 4th so the profiler captures it
    zero_cnt_kernel<<<nb, 256>>>(n);
    hist_kernel<<<eb, 256>>>(ei, ne);
    dinv_kernel<<<nb, 256>>>(n);
    gemm_kernel<64, 128, false, false, true><<<(n + 63) / 64, 256>>>(x, W1, n, 128, 128);
    scan_pass1<<<sb, SCAN_TILE>>>(n);
    scan_pass2<<<1, SCAN_TILE>>>(sb, n);
    scan_pass3<<<sb, SCAN_TILE>>>(n);
    fill_kernel<<<eb, 256>>>(ei, ne);
    padw3_kernel<<<32, 256>>>(W3);

    // layer 1 aggregation (fp16 h)
    agg128_kernel<<<wb, 256>>>(b1, n, 1);
    // layer 2
    gemm_kernel<64, 128, true, false, true><<<(n + 63) / 64, 256>>>(nullptr, W2, n, 128, 128);
    agg128_kernel<<<wb, 256>>>(b2, n, 1);
    // layer 3 (fp32 path, N padded 40 -> 64)
    gemm_kernel<128, 64, true, true, false><<<(n + 127) / 128, 256>>>(nullptr, nullptr, n, 64, 64);
    agg40_softmax_kernel<<<wb, 256>>>(b3, out, n);
}

// round 6
// speedup vs baseline: 1.5932x; 1.2284x over previous
#include <cuda_runtime.h>
#include <cuda_bf16.h>
#include <cuda_fp16.h>
#include <math.h>

#define MAXN 50000
#define MAXE 1600000
#define SCAN_TILE 256
#define MAXB ((MAXN + SCAN_TILE - 1) / SCAN_TILE)

// ---------------- scratch ----------------------------------------------------
__device__ __align__(16) float  g_h[MAXN * 128];    // fp32 GEMM out (layer3, stride 64)
__device__ __align__(16) __half g_h16[MAXN * 128];  // fp16 GEMM out (layers 1-2)
__device__ __align__(16) float  g_a[MAXN * 128];    // aggregation outputs
__device__ __align__(16) float  g_w3pad[128 * 64];  // zero-padded W3 (128x40 -> 128x64)
__device__ __align__(16) float  g_dinv[MAXN];
__device__ int   g_cnt[MAXN];
__device__ int   g_rowptr[MAXN + 1];
__device__ int   g_cursor[MAXN];
__device__ int   g_srcidx[MAXE];
__device__ int   g_bsum[MAXB];
__device__ int   g_boff[MAXB];

// ---------------- helpers ---------------------------------------------------
__device__ __forceinline__ float2 ffma2(float2 a, float2 b, float2 c) {
    unsigned long long A = *reinterpret_cast<unsigned long long*>(&a);
    unsigned long long B = *reinterpret_cast<unsigned long long*>(&b);
    unsigned long long C = *reinterpret_cast<unsigned long long*>(&c);
    unsigned long long D;
    asm("fma.rn.f32x2 %0, %1, %2, %3;" : "=l"(D) : "l"(A), "l"(B), "l"(C));
    return *reinterpret_cast<float2*>(&D);
}

// ---------------- graph preprocessing ---------------------------------------
__global__ void zero_cnt_kernel(int n) {
    int i = blockIdx.x * blockDim.x + threadIdx.x;
    if (i < n) g_cnt[i] = 0;
}

__global__ void hist_kernel(const int* __restrict__ ei, int ne) {
    int e = blockIdx.x * blockDim.x + threadIdx.x;
    if (e < ne) {
        int d = ei[ne + e];
        atomicAdd(&g_cnt[d], 1);
    }
}

__global__ void dinv_kernel(int n) {
    int i = blockIdx.x * blockDim.x + threadIdx.x;
    if (i < n) g_dinv[i] = rsqrtf((float)(g_cnt[i] + 1));
}

__global__ void scan_pass1(int n) {
    __shared__ int sh[SCAN_TILE];
    int t = threadIdx.x;
    int i = blockIdx.x * SCAN_TILE + t;
    int v = (i < n) ? g_cnt[i] : 0;
    sh[t] = v;
    __syncthreads();
    for (int off = SCAN_TILE / 2; off > 0; off >>= 1) {
        if (t < off) sh[t] += sh[t + off];
        __syncthreads();
    }
    if (t == 0) g_bsum[blockIdx.x] = sh[0];
}

__global__ void scan_pass2(int nb, int n) {
    __shared__ int sh[SCAN_TILE];
    int t = threadIdx.x;
    int v = (t < nb) ? g_bsum[t] : 0;
    sh[t] = v;
    __syncthreads();
    for (int off = 1; off < SCAN_TILE; off <<= 1) {
        int u = (t >= off) ? sh[t - off] : 0;
        __syncthreads();
        sh[t] += u;
        __syncthreads();
    }
    if (t < nb) g_boff[t] = sh[t] - v;
    if (t == nb - 1) g_rowptr[n] = sh[t];
}

__global__ void scan_pass3(int n) {
    __shared__ int sh[SCAN_TILE];
    int t = threadIdx.x;
    int i = blockIdx.x * SCAN_TILE + t;
    int v = (i < n) ? g_cnt[i] : 0;
    sh[t] = v;
    __syncthreads();
    for (int off = 1; off < SCAN_TILE; off <<= 1) {
        int u = (t >= off) ? sh[t - off] : 0;
        __syncthreads();
        sh[t] += u;
        __syncthreads();
    }
    if (i < n) {
        int excl = g_boff[blockIdx.x] + sh[t] - v;
        g_rowptr[i] = excl;
        g_cursor[i] = excl;
    }
}

__global__ void fill_kernel(const int* __restrict__ ei, int ne) {
    int e = blockIdx.x * blockDim.x + threadIdx.x;
    if (e < ne) {
        int s = ei[e];
        int d = ei[ne + e];
        int pos = atomicAdd(&g_cursor[d], 1);
        g_srcidx[pos] = s;
    }
}

__global__ void padw3_kernel(const float* __restrict__ W3) {
    int i = blockIdx.x * blockDim.x + threadIdx.x;
    if (i < 128 * 64) {
        int r = i >> 6, c = i & 63;
        g_w3pad[i] = (c < 40) ? W3[r * 40 + c] : 0.0f;
    }
}

// ---------------- GEMM: C = A[M x 128] @ B[128 x BN], BM=128, 256 threads ---
// Each thread: 8 rows (ty*4 + {0..3, 64..67}) x 4*CG cols (tx*4 + g*64).
// Per kk: 64B LDS per 32 FFMA2 -> LDS/FMA balanced on sm_103a.
template <int BN, bool A_INTERNAL, bool B_INTERNAL, bool OUT_HALF>
__global__ void gemm_kernel(const float* __restrict__ Aext,
                            const float* __restrict__ Bext,
                            int M, int ldb, int ldc) {
    const float* __restrict__ A = A_INTERNAL ? (const float*)g_a : Aext;
    const float* __restrict__ B = B_INTERNAL ? (const float*)g_w3pad : Bext;

    constexpr int BM = 128;
    constexpr int CG = BN / 64;            // col groups (1 or 2)
    __shared__ __align__(16) float As[16][BM + 4];
    __shared__ __align__(16) float Bs[16][BN];

    int tid = threadIdx.x;
    int tx = tid & 15;       // 0..15
    int ty = tid >> 4;       // 0..15
    int rowBase = blockIdx.x * BM;

    float2 acc[2][4][CG][2];
#pragma unroll
    for (int rg = 0; rg < 2; rg++)
#pragma unroll
        for (int i = 0; i < 4; i++)
#pragma unroll
            for (int g = 0; g < CG; g++) {
                acc[rg][i][g][0] = make_float2(0.f, 0.f);
                acc[rg][i][g][1] = make_float2(0.f, 0.f);
            }

    for (int k0 = 0; k0 < 128; k0 += 16) {
        // A tile: 128 rows x 16 k, transposed into As[k][row]
#pragma unroll
        for (int l = 0; l < 2; l++) {
            int idx = tid + l * 256;           // 0..511
            int r = idx >> 2;                  // 0..127
            int kq = idx & 3;                  // 0..3 (4 k each)
            float4 v = make_float4(0.f, 0.f, 0.f, 0.f);
            int grow = rowBase + r;
            if (grow < M) v = *(const float4*)&A[grow * 128 + k0 + kq * 4];
            As[kq * 4 + 0][r] = v.x;
            As[kq * 4 + 1][r] = v.y;
            As[kq * 4 + 2][r] = v.z;
            As[kq * 4 + 3][r] = v.w;
        }
        // B tile: 16 x BN
        constexpr int BF4 = (16 * BN / 4) / 256;  // 2 for BN=128, 1 for BN=64
#pragma unroll
        for (int l = 0; l < BF4; l++) {
            int idx = tid + l * 256;
            int r = idx / (BN / 4);
            int c4 = idx % (BN / 4);
            *(float4*)&Bs[r][c4 * 4] = *(const float4*)&B[(k0 + r) * ldb + c4 * 4];
        }
        __syncthreads();
#pragma unroll
        for (int kk = 0; kk < 16; kk++) {
            float4 a[2];
            a[0] = *(const float4*)&As[kk][ty * 4];
            a[1] = *(const float4*)&As[kk][ty * 4 + 64];
            float2 bp[CG][2];
#pragma unroll
            for (int g = 0; g < CG; g++) {
                float4 b = *(const float4*)&Bs[kk][tx * 4 + g * 64];
                bp[g][0] = make_float2(b.x, b.y);
                bp[g][1] = make_float2(b.z, b.w);
            }
#pragma unroll
            for (int rg = 0; rg < 2; rg++) {
                float am[4] = {a[rg].x, a[rg].y, a[rg].z, a[rg].w};
#pragma unroll
                for (int i = 0; i < 4; i++) {
                    float2 a2 = make_float2(am[i], am[i]);
#pragma unroll
                    for (int g = 0; g < CG; g++) {
                        acc[rg][i][g][0] = ffma2(a2, bp[g][0], acc[rg][i][g][0]);
                        acc[rg][i][g][1] = ffma2(a2, bp[g][1], acc[rg][i][g][1]);
                    }
                }
            }
        }
        __syncthreads();
    }
    // epilogue
#pragma unroll
    for (int rg = 0; rg < 2; rg++)
#pragma unroll
        for (int i = 0; i < 4; i++) {
            int grow = rowBase + ty * 4 + rg * 64 + i;
            if (grow >= M) continue;
#pragma unroll
            for (int g = 0; g < CG; g++) {
                int c = tx * 4 + g * 64;
                if (OUT_HALF) {
                    __half2 h0 = __float22half2_rn(acc[rg][i][g][0]);
                    __half2 h1 = __float22half2_rn(acc[rg][i][g][1]);
                    uint2 pk;
                    pk.x = *reinterpret_cast<unsigned*>(&h0);
                    pk.y = *reinterpret_cast<unsigned*>(&h1);
                    *(uint2*)&g_h16[grow * ldc + c] = pk;
                } else {
                    float4 o = make_float4(acc[rg][i][g][0].x, acc[rg][i][g][0].y,
                                           acc[rg][i][g][1].x, acc[rg][i][g][1].y);
                    *(float4*)&g_h[grow * ldc + c] = o;
                }
            }
        }
}

// ---------------- aggregation (F=128, fp16 source), warp per node -----------
__device__ __forceinline__ float4 half4_to_float4(uint2 raw) {
    __half2 p0 = *reinterpret_cast<__half2*>(&raw.x);
    __half2 p1 = *reinterpret_cast<__half2*>(&raw.y);
    float2 f0 = __half22float2(p0);
    float2 f1 = __half22float2(p1);
    return make_float4(f0.x, f0.y, f1.x, f1.y);
}

__global__ void agg128_kernel(const float* __restrict__ bias, int n, int do_relu) {
    int gw = (blockIdx.x * blockDim.x + threadIdx.x) >> 5;
    if (gw >= n) return;
    int lane = threadIdx.x & 31;
    const uint2* __restrict__ hv = (const uint2*)g_h16;

    float dd = g_dinv[gw];
    float ws = dd * dd;
    float4 v = half4_to_float4(hv[gw * 32 + lane]);
    float4 acc = make_float4(v.x * ws, v.y * ws, v.z * ws, v.w * ws);

    int beg = g_rowptr[gw];
    int end = g_rowptr[gw + 1];
    int i = beg;
    for (; i + 3 < end; i += 4) {
        int s0 = g_srcidx[i], s1 = g_srcidx[i + 1], s2 = g_srcidx[i + 2], s3 = g_srcidx[i + 3];
        float n0 = g_dinv[s0] * dd, n1 = g_dinv[s1] * dd, n2 = g_dinv[s2] * dd, n3 = g_dinv[s3] * dd;
        uint2 r0 = hv[s0 * 32 + lane];
        uint2 r1 = hv[s1 * 32 + lane];
        uint2 r2 = hv[s2 * 32 + lane];
        uint2 r3 = hv[s3 * 32 + lane];
        float4 v0 = half4_to_float4(r0);
        float4 v1 = half4_to_float4(r1);
        float4 v2 = half4_to_float4(r2);
        float4 v3 = half4_to_float4(r3);
        acc.x += n0 * v0.x + n1 * v1.x + n2 * v2.x + n3 * v3.x;
        acc.y += n0 * v0.y + n1 * v1.y + n2 * v2.y + n3 * v3.y;
        acc.z += n0 * v0.z + n1 * v1.z + n2 * v2.z + n3 * v3.z;
        acc.w += n0 * v0.w + n1 * v1.w + n2 * v2.w + n3 * v3.w;
    }
    for (; i < end; i++) {
        int s = g_srcidx[i];
        float nw = g_dinv[s] * dd;
        float4 vv = half4_to_float4(hv[s * 32 + lane]);
        acc.x += nw * vv.x;
        acc.y += nw * vv.y;
        acc.z += nw * vv.z;
        acc.w += nw * vv.w;
    }
    float4 b = ((const float4*)bias)[lane];
    acc.x += b.x; acc.y += b.y; acc.z += b.z; acc.w += b.w;
    if (do_relu) {
        acc.x = fmaxf(acc.x, 0.f);
        acc.y = fmaxf(acc.y, 0.f);
        acc.z = fmaxf(acc.z, 0.f);
        acc.w = fmaxf(acc.w, 0.f);
    }
    ((float4*)g_a)[gw * 32 + lane] = acc;
}

// ---------------- layer 3 aggregation (F=40, fp32 h stride 64) + softmax ----
__global__ void agg40_softmax_kernel(const float* __restrict__ b3,
                                     float* __restrict__ out, int n) {
    int gw = (blockIdx.x * blockDim.x + threadIdx.x) >> 5;
    if (gw >= n) return;
    int lane = threadIdx.x & 31;
    bool act = lane < 20;
    const float2* __restrict__ hv = (const float2*)g_h;

    float dd = g_dinv[gw];
    float ws = dd * dd;
    float2 acc = make_float2(0.f, 0.f);
    if (act) {
        float2 v = hv[gw * 32 + lane];
        acc.x = v.x * ws;
        acc.y = v.y * ws;
    }
    int beg = g_rowptr[gw];
    int end = g_rowptr[gw + 1];
    int i = beg;
    for (; i + 1 < end; i += 2) {
        int s0 = g_srcidx[i], s1 = g_srcidx[i + 1];
        float n0 = g_dinv[s0] * dd, n1 = g_dinv[s1] * dd;
        if (act) {
            float2 v0 = hv[s0 * 32 + lane];
            float2 v1 = hv[s1 * 32 + lane];
            acc.x += n0 * v0.x + n1 * v1.x;
            acc.y += n0 * v0.y + n1 * v1.y;
        }
    }
    if (i < end) {
        int s = g_srcidx[i];
        float nw = g_dinv[s] * dd;
        if (act) {
            float2 v = hv[s * 32 + lane];
            acc.x += nw * v.x;
            acc.y += nw * v.y;
        }
    }
    if (act) {
        acc.x += b3[lane * 2];
        acc.y += b3[lane * 2 + 1];
    }
    float m = act ? fmaxf(acc.x, acc.y) : -INFINITY;
#pragma unroll
    for (int off = 16; off > 0; off >>= 1) m = fmaxf(m, __shfl_xor_sync(0xFFFFFFFFu, m, off));
    float se = act ? (expf(acc.x - m) + expf(acc.y - m)) : 0.f;
#pragma unroll
    for (int off = 16; off > 0; off >>= 1) se += __shfl_xor_sync(0xFFFFFFFFu, se, off);
    float ls = m + logf(se);
    if (act) {
        out[gw * 40 + lane * 2 + 0] = acc.x - ls;
        out[gw * 40 + lane * 2 + 1] = acc.y - ls;
    }
}

// ---------------- launch -----------------------------------------------------
extern "C" void kernel_launch(void* const* d_in, const int* in_sizes, int n_in,
                              void* d_out, int out_size) {
    const float* x = (const float*)d_in[0];
    const int* ei = (const int*)d_in[1];
    const float* W1 = (const float*)d_in[2];
    const float* b1 = (const float*)d_in[3];
    const float* W2 = (const float*)d_in[4];
    const float* b2 = (const float*)d_in[5];
    const float* W3 = (const float*)d_in[6];
    const float* b3 = (const float*)d_in[7];
    float* out = (float*)d_out;

    const int n = in_sizes[0] / 128;   // 50000
    const int ne = in_sizes[1] / 2;    // 1600000

    int nb = (n + 255) / 256;
    int eb = (ne + 255) / 256;
    int wb = (n + 7) / 8;
    int sb = (n + SCAN_TILE - 1) / SCAN_TILE;
    int gb = (n + 127) / 128;

    // preprocessing; layer-1 GEMM at 4th slot (profiler captures launch #4)
    zero_cnt_kernel<<<nb, 256>>>(n);
    hist_kernel<<<eb, 256>>>(ei, ne);
    dinv_kernel<<<nb, 256>>>(n);
    gemm_kernel<128, false, false, true><<<gb, 256>>>(x, W1, n, 128, 128);
    scan_pass1<<<sb, SCAN_TILE>>>(n);
    scan_pass2<<<1, SCAN_TILE>>>(sb, n);
    scan_pass3<<<sb, SCAN_TILE>>>(n);
    fill_kernel<<<eb, 256>>>(ei, ne);
    padw3_kernel<<<32, 256>>>(W3);

    // layer 1 aggregation (fp16 h)
    agg128_kernel<<<wb, 256>>>(b1, n, 1);
    // layer 2
    gemm_kernel<128, true, false, true><<<gb, 256>>>(nullptr, W2, n, 128, 128);
    agg128_kernel<<<wb, 256>>>(b2, n, 1);
    // layer 3 (fp32 path, N padded 40 -> 64)
    gemm_kernel<64, true, true, false><<<gb, 256>>>(nullptr, nullptr, n, 64, 64);
    agg40_softmax_kernel<<<wb, 256>>>(b3, out, n);
}

// round 7
// speedup vs baseline: 1.9024x; 1.1941x over previous
#include <cuda_runtime.h>
#include <cuda_bf16.h>
#include <cuda_fp16.h>
#include <math.h>

#define MAXN 50000
#define MAXE 1600000
#define SCAN_TILE 256
#define MAXB ((MAXN + SCAN_TILE - 1) / SCAN_TILE)

// ---------------- scratch ----------------------------------------------------
__device__ __align__(16) float  g_h[MAXN * 64];     // fp32 GEMM out (layer3, stride 64)
__device__ __align__(16) __half g_h16[MAXN * 128];  // fp16 GEMM out (layers 1-2)
__device__ __align__(16) __half g_a16[MAXN * 128];  // fp16 aggregation outputs
__device__ __align__(16) __half g_x16[MAXN * 128];  // fp16 copy of x
__device__ __align__(16) float  g_w3pad[128 * 64];  // zero-padded W3 (128x40 -> 128x64)
__device__ __align__(16) float  g_dinv[MAXN];
__device__ int   g_cnt[MAXN];
__device__ int   g_rowptr[MAXN + 1];
__device__ int   g_cursor[MAXN];
__device__ int   g_srcidx[MAXE];
__device__ int   g_bsum[MAXB];
__device__ int   g_boff[MAXB];

// ---------------- graph preprocessing ---------------------------------------
__global__ void zero_cnt_kernel(int n) {
    int i = blockIdx.x * blockDim.x + threadIdx.x;
    if (i < n) g_cnt[i] = 0;
}

__global__ void hist_kernel(const int* __restrict__ ei, int ne) {
    int e = blockIdx.x * blockDim.x + threadIdx.x;
    if (e < ne) {
        int d = ei[ne + e];
        atomicAdd(&g_cnt[d], 1);
    }
}

__global__ void dinv_kernel(int n) {
    int i = blockIdx.x * blockDim.x + threadIdx.x;
    if (i < n) g_dinv[i] = rsqrtf((float)(g_cnt[i] + 1));
}

__global__ void scan_pass1(int n) {
    __shared__ int sh[SCAN_TILE];
    int t = threadIdx.x;
    int i = blockIdx.x * SCAN_TILE + t;
    int v = (i < n) ? g_cnt[i] : 0;
    sh[t] = v;
    __syncthreads();
    for (int off = SCAN_TILE / 2; off > 0; off >>= 1) {
        if (t < off) sh[t] += sh[t + off];
        __syncthreads();
    }
    if (t == 0) g_bsum[blockIdx.x] = sh[0];
}

__global__ void scan_pass2(int nb, int n) {
    __shared__ int sh[SCAN_TILE];
    int t = threadIdx.x;
    int v = (t < nb) ? g_bsum[t] : 0;
    sh[t] = v;
    __syncthreads();
    for (int off = 1; off < SCAN_TILE; off <<= 1) {
        int u = (t >= off) ? sh[t - off] : 0;
        __syncthreads();
        sh[t] += u;
        __syncthreads();
    }
    if (t < nb) g_boff[t] = sh[t] - v;
    if (t == nb - 1) g_rowptr[n] = sh[t];
}

__global__ void scan_pass3(int n) {
    __shared__ int sh[SCAN_TILE];
    int t = threadIdx.x;
    int i = blockIdx.x * SCAN_TILE + t;
    int v = (i < n) ? g_cnt[i] : 0;
    sh[t] = v;
    __syncthreads();
    for (int off = 1; off < SCAN_TILE; off <<= 1) {
        int u = (t >= off) ? sh[t - off] : 0;
        __syncthreads();
        sh[t] += u;
        __syncthreads();
    }
    if (i < n) {
        int excl = g_boff[blockIdx.x] + sh[t] - v;
        g_rowptr[i] = excl;
        g_cursor[i] = excl;
    }
}

__global__ void fill_kernel(const int* __restrict__ ei, int ne) {
    int e = blockIdx.x * blockDim.x + threadIdx.x;
    if (e < ne) {
        int s = ei[e];
        int d = ei[ne + e];
        int pos = atomicAdd(&g_cursor[d], 1);
        g_srcidx[pos] = s;
    }
}

__global__ void padw3_kernel(const float* __restrict__ W3) {
    int i = blockIdx.x * blockDim.x + threadIdx.x;
    if (i < 128 * 64) {
        int r = i >> 6, c = i & 63;
        g_w3pad[i] = (c < 40) ? W3[r * 40 + c] : 0.0f;
    }
}

// x (fp32) -> g_x16 (fp16), 8 elems per thread
__global__ void x16_kernel(const float* __restrict__ x, int total8) {
    int i = blockIdx.x * blockDim.x + threadIdx.x;
    if (i < total8) {
        float4 v0 = *(const float4*)&x[i * 8];
        float4 v1 = *(const float4*)&x[i * 8 + 4];
        __half2 h[4];
        h[0] = __floats2half2_rn(v0.x, v0.y);
        h[1] = __floats2half2_rn(v0.z, v0.w);
        h[2] = __floats2half2_rn(v1.x, v1.y);
        h[3] = __floats2half2_rn(v1.z, v1.w);
        *(uint4*)&g_x16[i * 8] = *(uint4*)h;
    }
}

// ---------------- HMMA GEMM: C = A[M x 128](fp16) @ B[128 x BN] -------------
__device__ __forceinline__ void mma16816(float* c, const unsigned* a, const unsigned* b) {
    asm volatile(
        "mma.sync.aligned.m16n8k16.row.col.f32.f16.f16.f32 "
        "{%0,%1,%2,%3}, {%4,%5,%6,%7}, {%8,%9}, {%0,%1,%2,%3};"
        : "+f"(c[0]), "+f"(c[1]), "+f"(c[2]), "+f"(c[3])
        : "r"(a[0]), "r"(a[1]), "r"(a[2]), "r"(a[3]), "r"(b[0]), "r"(b[1]));
}

// BM=128, 256 threads (8 warps). Warp grid: WARPS_M x WARPS_N.
// m16n8k16 fragments loaded via conflict-free LDS.32 (padded stride 136).
template <int BN, bool A_IS_X, bool B_INTERNAL, bool OUT_HALF>
__global__ void gemm_hmma(const float* __restrict__ Bext, int M, int ldb, int ldc) {
    constexpr int LDA = 136;            // halfs; 272B stride -> conflict-free
    constexpr int WARPS_N = BN / 32;    // 4 (BN=128) or 2 (BN=64)
    constexpr int WARPS_M = 8 / WARPS_N;
    constexpr int MT = (128 / WARPS_M) / 16;  // m16 tiles per warp: 4 or 2

    extern __shared__ __half smem[];
    __half* As = smem;                  // [128][LDA]
    __half* Bs = smem + 128 * LDA;      // [BN][LDA]

    const __half* __restrict__ A = A_IS_X ? (const __half*)g_x16 : (const __half*)g_a16;
    const float* __restrict__ B = B_INTERNAL ? (const float*)g_w3pad : Bext;

    int tid = threadIdx.x;
    int rowBase = blockIdx.x * 128;

    // stage A tile (128 x 128 halfs) as 16B chunks
#pragma unroll
    for (int l = 0; l < 8; l++) {
        int idx = tid + l * 256;
        int r = idx >> 4;
        int c = (idx & 15) * 8;
        uint4 v = make_uint4(0, 0, 0, 0);
        int grow = rowBase + r;
        if (grow < M) v = *(const uint4*)&A[grow * 128 + c];
        *(uint4*)&As[r * LDA + c] = v;
    }
    // stage B transposed: Bs[n][k] = fp16(B[k][n])
    for (int idx = tid; idx < 128 * BN; idx += 256) {
        int k = idx / BN, nn = idx % BN;
        Bs[nn * LDA + k] = __float2half(B[k * ldb + nn]);
    }
    __syncthreads();

    int wid = tid >> 5, lane = tid & 31;
    int g = lane >> 2, t = lane & 3;
    int wm = (wid / WARPS_N) * (MT * 16);
    int wn = (wid % WARPS_N) * 32;

    float acc[MT][4][4];
#pragma unroll
    for (int mi = 0; mi < MT; mi++)
#pragma unroll
        for (int ni = 0; ni < 4; ni++)
#pragma unroll
            for (int q = 0; q < 4; q++) acc[mi][ni][q] = 0.f;

#pragma unroll
    for (int ks = 0; ks < 8; ks++) {
        int k0 = ks * 16;
        unsigned afr[MT][4], bfr[4][2];
#pragma unroll
        for (int mi = 0; mi < MT; mi++) {
            const __half* base = &As[(wm + mi * 16 + g) * LDA + k0 + 2 * t];
            afr[mi][0] = *(const unsigned*)(base);
            afr[mi][1] = *(const unsigned*)(base + 8 * LDA);
            afr[mi][2] = *(const unsigned*)(base + 8);
            afr[mi][3] = *(const unsigned*)(base + 8 * LDA + 8);
        }
#pragma unroll
        for (int ni = 0; ni < 4; ni++) {
            const __half* bb = &Bs[(wn + ni * 8 + g) * LDA + k0 + 2 * t];
            bfr[ni][0] = *(const unsigned*)(bb);
            bfr[ni][1] = *(const unsigned*)(bb + 8);
        }
#pragma unroll
        for (int mi = 0; mi < MT; mi++)
#pragma unroll
            for (int ni = 0; ni < 4; ni++)
                mma16816(acc[mi][ni], afr[mi], bfr[ni]);
    }

    // epilogue
#pragma unroll
    for (int mi = 0; mi < MT; mi++) {
#pragma unroll
        for (int ni = 0; ni < 4; ni++) {
            int r0 = rowBase + wm + mi * 16 + g;
            int c = wn + ni * 8 + 2 * t;
            if (OUT_HALF) {
                if (r0 < M) {
                    __half2 h = __floats2half2_rn(acc[mi][ni][0], acc[mi][ni][1]);
                    *(__half2*)&g_h16[r0 * ldc + c] = h;
                }
                if (r0 + 8 < M) {
                    __half2 h = __floats2half2_rn(acc[mi][ni][2], acc[mi][ni][3]);
                    *(__half2*)&g_h16[(r0 + 8) * ldc + c] = h;
                }
            } else {
                if (r0 < M)
                    *(float2*)&g_h[r0 * ldc + c] = make_float2(acc[mi][ni][0], acc[mi][ni][1]);
                if (r0 + 8 < M)
                    *(float2*)&g_h[(r0 + 8) * ldc + c] = make_float2(acc[mi][ni][2], acc[mi][ni][3]);
            }
        }
    }
}

// ---------------- aggregation (F=128, fp16 in/out), warp per node -----------
__device__ __forceinline__ float4 half4_to_float4(uint2 raw) {
    __half2 p0 = *reinterpret_cast<__half2*>(&raw.x);
    __half2 p1 = *reinterpret_cast<__half2*>(&raw.y);
    float2 f0 = __half22float2(p0);
    float2 f1 = __half22float2(p1);
    return make_float4(f0.x, f0.y, f1.x, f1.y);
}

__global__ void agg128_kernel(const float* __restrict__ bias, int n, int do_relu) {
    int gw = (blockIdx.x * blockDim.x + threadIdx.x) >> 5;
    if (gw >= n) return;
    int lane = threadIdx.x & 31;
    const uint2* __restrict__ hv = (const uint2*)g_h16;

    float dd = g_dinv[gw];
    float ws = dd * dd;
    float4 v = half4_to_float4(hv[gw * 32 + lane]);
    float4 acc = make_float4(v.x * ws, v.y * ws, v.z * ws, v.w * ws);

    int beg = g_rowptr[gw];
    int end = g_rowptr[gw + 1];
    int i = beg;
    for (; i + 3 < end; i += 4) {
        int s0 = g_srcidx[i], s1 = g_srcidx[i + 1], s2 = g_srcidx[i + 2], s3 = g_srcidx[i + 3];
        float n0 = g_dinv[s0] * dd, n1 = g_dinv[s1] * dd, n2 = g_dinv[s2] * dd, n3 = g_dinv[s3] * dd;
        uint2 r0 = hv[s0 * 32 + lane];
        uint2 r1 = hv[s1 * 32 + lane];
        uint2 r2 = hv[s2 * 32 + lane];
        uint2 r3 = hv[s3 * 32 + lane];
        float4 v0 = half4_to_float4(r0);
        float4 v1 = half4_to_float4(r1);
        float4 v2 = half4_to_float4(r2);
        float4 v3 = half4_to_float4(r3);
        acc.x += n0 * v0.x + n1 * v1.x + n2 * v2.x + n3 * v3.x;
        acc.y += n0 * v0.y + n1 * v1.y + n2 * v2.y + n3 * v3.y;
        acc.z += n0 * v0.z + n1 * v1.z + n2 * v2.z + n3 * v3.z;
        acc.w += n0 * v0.w + n1 * v1.w + n2 * v2.w + n3 * v3.w;
    }
    for (; i < end; i++) {
        int s = g_srcidx[i];
        float nw = g_dinv[s] * dd;
        float4 vv = half4_to_float4(hv[s * 32 + lane]);
        acc.x += nw * vv.x;
        acc.y += nw * vv.y;
        acc.z += nw * vv.z;
        acc.w += nw * vv.w;
    }
    float4 b = ((const float4*)bias)[lane];
    acc.x += b.x; acc.y += b.y; acc.z += b.z; acc.w += b.w;
    if (do_relu) {
        acc.x = fmaxf(acc.x, 0.f);
        acc.y = fmaxf(acc.y, 0.f);
        acc.z = fmaxf(acc.z, 0.f);
        acc.w = fmaxf(acc.w, 0.f);
    }
    __half2 o[2];
    o[0] = __floats2half2_rn(acc.x, acc.y);
    o[1] = __floats2half2_rn(acc.z, acc.w);
    *(uint2*)&g_a16[gw * 128 + lane * 4] = *(uint2*)o;
}

// ---------------- layer 3 aggregation (F=40, fp32 h stride 64) + softmax ----
__global__ void agg40_softmax_kernel(const float* __restrict__ b3,
                                     float* __restrict__ out, int n) {
    int gw = (blockIdx.x * blockDim.x + threadIdx.x) >> 5;
    if (gw >= n) return;
    int lane = threadIdx.x & 31;
    bool act = lane < 20;
    const float2* __restrict__ hv = (const float2*)g_h;

    float dd = g_dinv[gw];
    float ws = dd * dd;
    float2 acc = make_float2(0.f, 0.f);
    if (act) {
        float2 v = hv[gw * 32 + lane];
        acc.x = v.x * ws;
        acc.y = v.y * ws;
    }
    int beg = g_rowptr[gw];
    int end = g_rowptr[gw + 1];
    int i = beg;
    for (; i + 1 < end; i += 2) {
        int s0 = g_srcidx[i], s1 = g_srcidx[i + 1];
        float n0 = g_dinv[s0] * dd, n1 = g_dinv[s1] * dd;
        if (act) {
            float2 v0 = hv[s0 * 32 + lane];
            float2 v1 = hv[s1 * 32 + lane];
            acc.x += n0 * v0.x + n1 * v1.x;
            acc.y += n0 * v0.y + n1 * v1.y;
        }
    }
    if (i < end) {
        int s = g_srcidx[i];
        float nw = g_dinv[s] * dd;
        if (act) {
            float2 v = hv[s * 32 + lane];
            acc.x += nw * v.x;
            acc.y += nw * v.y;
        }
    }
    if (act) {
        acc.x += b3[lane * 2];
        acc.y += b3[lane * 2 + 1];
    }
    float m = act ? fmaxf(acc.x, acc.y) : -INFINITY;
#pragma unroll
    for (int off = 16; off > 0; off >>= 1) m = fmaxf(m, __shfl_xor_sync(0xFFFFFFFFu, m, off));
    float se = act ? (expf(acc.x - m) + expf(acc.y - m)) : 0.f;
#pragma unroll
    for (int off = 16; off > 0; off >>= 1) se += __shfl_xor_sync(0xFFFFFFFFu, se, off);
    float ls = m + logf(se);
    if (act) {
        out[gw * 40 + lane * 2 + 0] = acc.x - ls;
        out[gw * 40 + lane * 2 + 1] = acc.y - ls;
    }
}

// ---------------- launch -----------------------------------------------------
extern "C" void kernel_launch(void* const* d_in, const int* in_sizes, int n_in,
                              void* d_out, int out_size) {
    const float* x = (const float*)d_in[0];
    const int* ei = (const int*)d_in[1];
    const float* W1 = (const float*)d_in[2];
    const float* b1 = (const float*)d_in[3];
    const float* W2 = (const float*)d_in[4];
    const float* b2 = (const float*)d_in[5];
    const float* W3 = (const float*)d_in[6];
    const float* b3 = (const float*)d_in[7];
    float* out = (float*)d_out;

    const int n = in_sizes[0] / 128;   // 50000
    const int ne = in_sizes[1] / 2;    // 1600000

    int nb = (n + 255) / 256;
    int eb = (ne + 255) / 256;
    int wb = (n + 7) / 8;
    int sb = (n + SCAN_TILE - 1) / SCAN_TILE;
    int gb = (n + 127) / 128;

    const int SMEM_128 = (128 + 128) * 136 * 2;  // 69632
    const int SMEM_64  = (128 + 64) * 136 * 2;   // 52224
    cudaFuncSetAttribute((const void*)gemm_hmma<128, true, false, true>,
                         cudaFuncAttributeMaxDynamicSharedMemorySize, SMEM_128);
    cudaFuncSetAttribute((const void*)gemm_hmma<128, false, false, true>,
                         cudaFuncAttributeMaxDynamicSharedMemorySize, SMEM_128);
    cudaFuncSetAttribute((const void*)gemm_hmma<64, false, true, false>,
                         cudaFuncAttributeMaxDynamicSharedMemorySize, SMEM_64);

    // preprocessing; layer-1 GEMM at 4th slot (profiler captures launch #4)
    zero_cnt_kernel<<<nb, 256>>>(n);
    hist_kernel<<<eb, 256>>>(ei, ne);
    x16_kernel<<<(n * 16 + 255) / 256, 256>>>(x, n * 16);
    gemm_hmma<128, true, false, true><<<gb, 256, SMEM_128>>>(W1, n, 128, 128);
    dinv_kernel<<<nb, 256>>>(n);
    scan_pass1<<<sb, SCAN_TILE>>>(n);
    scan_pass2<<<1, SCAN_TILE>>>(sb, n);
    scan_pass3<<<sb, SCAN_TILE>>>(n);
    fill_kernel<<<eb, 256>>>(ei, ne);
    padw3_kernel<<<32, 256>>>(W3);

    // layer 1 aggregation (fp16 h -> fp16 a)
    agg128_kernel<<<wb, 256>>>(b1, n, 1);
    // layer 2
    gemm_hmma<128, false, false, true><<<gb, 256, SMEM_128>>>(W2, n, 128, 128);
    agg128_kernel<<<wb, 256>>>(b2, n, 1);
    // layer 3 (fp32 out, N padded 40 -> 64)
    gemm_hmma<64, false, true, false><<<gb, 256, SMEM_64>>>(nullptr, n, 64, 64);
    agg40_softmax_kernel<<<wb, 256>>>(b3, out, n);
}

// round 10
// speedup vs baseline: 2.0094x; 1.0563x over previous
#include <cuda_runtime.h>
#include <cuda_bf16.h>
#include <cuda_fp16.h>
#include <math.h>

#define MAXN 50000
#define MAXE 1600000
#define SCAN_TILE 256
#define MAXB ((MAXN + SCAN_TILE - 1) / SCAN_TILE)

// ---------------- scratch ----------------------------------------------------
__device__ __align__(16) float  g_h[MAXN * 64];     // fp32 GEMM out (layer3, stride 64)
__device__ __align__(16) __half g_h16[MAXN * 128];  // fp16 GEMM out (layers 1-2)
__device__ __align__(16) __half g_a16[MAXN * 128];  // fp16 aggregation outputs
__device__ __align__(16) __half g_x16[MAXN * 128];  // fp16 copy of x
__device__ __align__(16) __half g_w1t[128 * 128];   // W1^T fp16 [n][k]
__device__ __align__(16) __half g_w2t[128 * 128];   // W2^T fp16 [n][k]
__device__ __align__(16) __half g_w3t[64 * 128];    // W3^T fp16 padded [n][k]
__device__ __align__(16) float  g_dinv[MAXN];
__device__ int   g_cnt[MAXN];
__device__ int   g_rowptr[MAXN + 1];
__device__ int   g_cursor[MAXN];
__device__ int   g_srcidx[MAXE];
__device__ int   g_bsum[MAXB];
__device__ int   g_boff[MAXB];

// ---------------- graph preprocessing ---------------------------------------
__global__ void zero_cnt_kernel(int n) {
    int i = blockIdx.x * blockDim.x + threadIdx.x;
    if (i < n) g_cnt[i] = 0;
}

__global__ void hist_kernel(const int* __restrict__ ei, int ne) {
    int e = blockIdx.x * blockDim.x + threadIdx.x;
    if (e < ne) {
        int d = ei[ne + e];
        atomicAdd(&g_cnt[d], 1);
    }
}

__global__ void dinv_kernel(int n) {
    int i = blockIdx.x * blockDim.x + threadIdx.x;
    if (i < n) g_dinv[i] = rsqrtf((float)(g_cnt[i] + 1));
}

__global__ void scan_pass1(int n) {
    __shared__ int sh[SCAN_TILE];
    int t = threadIdx.x;
    int i = blockIdx.x * SCAN_TILE + t;
    int v = (i < n) ? g_cnt[i] : 0;
    sh[t] = v;
    __syncthreads();
    for (int off = SCAN_TILE / 2; off > 0; off >>= 1) {
        if (t < off) sh[t] += sh[t + off];
        __syncthreads();
    }
    if (t == 0) g_bsum[blockIdx.x] = sh[0];
}

__global__ void scan_pass2(int nb, int n) {
    __shared__ int sh[SCAN_TILE];
    int t = threadIdx.x;
    int v = (t < nb) ? g_bsum[t] : 0;
    sh[t] = v;
    __syncthreads();
    for (int off = 1; off < SCAN_TILE; off <<= 1) {
        int u = (t >= off) ? sh[t - off] : 0;
        __syncthreads();
        sh[t] += u;
        __syncthreads();
    }
    if (t < nb) g_boff[t] = sh[t] - v;
    if (t == nb - 1) g_rowptr[n] = sh[t];
}

__global__ void scan_pass3(int n) {
    __shared__ int sh[SCAN_TILE];
    int t = threadIdx.x;
    int i = blockIdx.x * SCAN_TILE + t;
    int v = (i < n) ? g_cnt[i] : 0;
    sh[t] = v;
    __syncthreads();
    for (int off = 1; off < SCAN_TILE; off <<= 1) {
        int u = (t >= off) ? sh[t - off] : 0;
        __syncthreads();
        sh[t] += u;
        __syncthreads();
    }
    if (i < n) {
        int excl = g_boff[blockIdx.x] + sh[t] - v;
        g_rowptr[i] = excl;
        g_cursor[i] = excl;
    }
}

__global__ void fill_kernel(const int* __restrict__ ei, int ne) {
    int e = blockIdx.x * blockDim.x + threadIdx.x;
    if (e < ne) {
        int s = ei[e];
        int d = ei[ne + e];
        int pos = atomicAdd(&g_cursor[d], 1);
        g_srcidx[pos] = s;
    }
}

// x (fp32) -> g_x16 (fp16), 8 elems per thread
__global__ void x16_kernel(const float* __restrict__ x, int total8) {
    int i = blockIdx.x * blockDim.x + threadIdx.x;
    if (i < total8) {
        float4 v0 = *(const float4*)&x[i * 8];
        float4 v1 = *(const float4*)&x[i * 8 + 4];
        __half2 h[4];
        h[0] = __floats2half2_rn(v0.x, v0.y);
        h[1] = __floats2half2_rn(v0.z, v0.w);
        h[2] = __floats2half2_rn(v1.x, v1.y);
        h[3] = __floats2half2_rn(v1.z, v1.w);
        *(uint4*)&g_x16[i * 8] = *(uint4*)h;
    }
}

// W[128 x 128] fp32 -> transposed fp16 [n][k]; destination selected by SYMBOL
// inside device code (never pass a __device__ symbol as a host-side kernel arg:
// on GB300/ATS the host shadow address is silently dereferenceable -> wrong mem).
template <int WSEL>
__global__ void w128t_kernel(const float* __restrict__ W) {
    __half* out = (WSEL == 1) ? g_w1t : g_w2t;
    int i = blockIdx.x * blockDim.x + threadIdx.x;  // 16384
    int nn = i >> 7, k = i & 127;
    out[i] = __float2half(W[k * 128 + nn]);
}

// W3[128 x 40] fp32 -> transposed fp16 padded [64][128]
__global__ void w3t_kernel(const float* __restrict__ W3) {
    int i = blockIdx.x * blockDim.x + threadIdx.x;  // 8192
    int nn = i >> 7, k = i & 127;
    g_w3t[i] = (nn < 40) ? __float2half(W3[k * 40 + nn]) : __half(0.f);
}

// ---------------- HMMA GEMM: C = A[M x 128](fp16) @ B[128 x BN] -------------
__device__ __forceinline__ void mma16816(float* c, const unsigned* a, const unsigned* b) {
    asm volatile(
        "mma.sync.aligned.m16n8k16.row.col.f32.f16.f16.f32 "
        "{%0,%1,%2,%3}, {%4,%5,%6,%7}, {%8,%9}, {%0,%1,%2,%3};"
        : "+f"(c[0]), "+f"(c[1]), "+f"(c[2]), "+f"(c[3])
        : "r"(a[0]), "r"(a[1]), "r"(a[2]), "r"(a[3]), "r"(b[0]), "r"(b[1]));
}

// BM=128, 256 threads (8 warps) — round-7 proven structure.
// B staged from pre-transposed fp16 tables (uint4 copies).
template <int BN, bool A_IS_X, int WSEL, bool OUT_HALF>
__global__ void gemm_hmma(int M, int ldc) {
    constexpr int LDA = 136;            // halfs; conflict-free padded stride
    constexpr int WARPS_N = BN / 32;    // 4 (BN=128) or 2 (BN=64)
    constexpr int WARPS_M = 8 / WARPS_N;
    constexpr int MT = (128 / WARPS_M) / 16;  // 4 or 2

    extern __shared__ __half smem[];
    __half* As = smem;                  // [128][LDA]
    __half* Bs = smem + 128 * LDA;      // [BN][LDA]

    const __half* __restrict__ A = A_IS_X ? (const __half*)g_x16 : (const __half*)g_a16;
    const __half* __restrict__ Bt =
        (WSEL == 1) ? (const __half*)g_w1t :
        (WSEL == 2) ? (const __half*)g_w2t : (const __half*)g_w3t;

    int tid = threadIdx.x;
    int rowBase = blockIdx.x * 128;

    // stage A tile (128 x 128 halfs) as 16B chunks
#pragma unroll
    for (int l = 0; l < 8; l++) {
        int idx = tid + l * 256;
        int r = idx >> 4;
        int c = (idx & 15) * 8;
        uint4 v = make_uint4(0, 0, 0, 0);
        int grow = rowBase + r;
        if (grow < M) v = *(const uint4*)&A[grow * 128 + c];
        *(uint4*)&As[r * LDA + c] = v;
    }
    // stage B tile (BN x 128 halfs) from pre-transposed fp16 table
#pragma unroll
    for (int l = 0; l < BN / 16; l++) {
        int idx = tid + l * 256;
        int r = idx >> 4;
        int c = (idx & 15) * 8;
        *(uint4*)&Bs[r * LDA + c] = *(const uint4*)&Bt[r * 128 + c];
    }
    __syncthreads();

    int wid = tid >> 5, lane = tid & 31;
    int g = lane >> 2, t = lane & 3;
    int wm = (wid / WARPS_N) * (MT * 16);
    int wn = (wid % WARPS_N) * 32;

    float acc[MT][4][4];
#pragma unroll
    for (int mi = 0; mi < MT; mi++)
#pragma unroll
        for (int ni = 0; ni < 4; ni++)
#pragma unroll
            for (int q = 0; q < 4; q++) acc[mi][ni][q] = 0.f;

#pragma unroll
    for (int ks = 0; ks < 8; ks++) {
        int k0 = ks * 16;
        unsigned afr[MT][4], bfr[4][2];
#pragma unroll
        for (int mi = 0; mi < MT; mi++) {
            const __half* base = &As[(wm + mi * 16 + g) * LDA + k0 + 2 * t];
            afr[mi][0] = *(const unsigned*)(base);
            afr[mi][1] = *(const unsigned*)(base + 8 * LDA);
            afr[mi][2] = *(const unsigned*)(base + 8);
            afr[mi][3] = *(const unsigned*)(base + 8 * LDA + 8);
        }
#pragma unroll
        for (int ni = 0; ni < 4; ni++) {
            const __half* bb = &Bs[(wn + ni * 8 + g) * LDA + k0 + 2 * t];
            bfr[ni][0] = *(const unsigned*)(bb);
            bfr[ni][1] = *(const unsigned*)(bb + 8);
        }
#pragma unroll
        for (int mi = 0; mi < MT; mi++)
#pragma unroll
            for (int ni = 0; ni < 4; ni++)
                mma16816(acc[mi][ni], afr[mi], bfr[ni]);
    }

    // epilogue (fp16 for layers 1-2, fp32 for layer 3)
#pragma unroll
    for (int mi = 0; mi < MT; mi++) {
#pragma unroll
        for (int ni = 0; ni < 4; ni++) {
            int r0 = rowBase + wm + mi * 16 + g;
            int c = wn + ni * 8 + 2 * t;
            if (OUT_HALF) {
                if (r0 < M) {
                    __half2 h = __floats2half2_rn(acc[mi][ni][0], acc[mi][ni][1]);
                    *(__half2*)&g_h16[r0 * ldc + c] = h;
                }
                if (r0 + 8 < M) {
                    __half2 h = __floats2half2_rn(acc[mi][ni][2], acc[mi][ni][3]);
                    *(__half2*)&g_h16[(r0 + 8) * ldc + c] = h;
                }
            } else {
                if (r0 < M)
                    *(float2*)&g_h[r0 * ldc + c] = make_float2(acc[mi][ni][0], acc[mi][ni][1]);
                if (r0 + 8 < M)
                    *(float2*)&g_h[(r0 + 8) * ldc + c] = make_float2(acc[mi][ni][2], acc[mi][ni][3]);
            }
        }
    }
}

// ---------------- aggregation (F=128, fp16 in/out), warp per node -----------
__device__ __forceinline__ float4 half4_to_float4(uint2 raw) {
    __half2 p0 = *reinterpret_cast<__half2*>(&raw.x);
    __half2 p1 = *reinterpret_cast<__half2*>(&raw.y);
    float2 f0 = __half22float2(p0);
    float2 f1 = __half22float2(p1);
    return make_float4(f0.x, f0.y, f1.x, f1.y);
}

__global__ void agg128_kernel(const float* __restrict__ bias, int n, int do_relu) {
    int gw = (blockIdx.x * blockDim.x + threadIdx.x) >> 5;
    if (gw >= n) return;
    int lane = threadIdx.x & 31;
    const uint2* __restrict__ hv = (const uint2*)g_h16;

    float dd = g_dinv[gw];
    float ws = dd * dd;
    float4 v = half4_to_float4(hv[gw * 32 + lane]);
    float4 acc = make_float4(v.x * ws, v.y * ws, v.z * ws, v.w * ws);

    int beg = g_rowptr[gw];
    int end = g_rowptr[gw + 1];
    int i = beg;
    for (; i + 3 < end; i += 4) {
        int s0 = g_srcidx[i], s1 = g_srcidx[i + 1], s2 = g_srcidx[i + 2], s3 = g_srcidx[i + 3];
        float n0 = g_dinv[s0] * dd, n1 = g_dinv[s1] * dd, n2 = g_dinv[s2] * dd, n3 = g_dinv[s3] * dd;
        uint2 r0 = hv[s0 * 32 + lane];
        uint2 r1 = hv[s1 * 32 + lane];
        uint2 r2 = hv[s2 * 32 + lane];
        uint2 r3 = hv[s3 * 32 + lane];
        float4 v0 = half4_to_float4(r0);
        float4 v1 = half4_to_float4(r1);
        float4 v2 = half4_to_float4(r2);
        float4 v3 = half4_to_float4(r3);
        acc.x += n0 * v0.x + n1 * v1.x + n2 * v2.x + n3 * v3.x;
        acc.y += n0 * v0.y + n1 * v1.y + n2 * v2.y + n3 * v3.y;
        acc.z += n0 * v0.z + n1 * v1.z + n2 * v2.z + n3 * v3.z;
        acc.w += n0 * v0.w + n1 * v1.w + n2 * v2.w + n3 * v3.w;
    }
    for (; i < end; i++) {
        int s = g_srcidx[i];
        float nw = g_dinv[s] * dd;
        float4 vv = half4_to_float4(hv[s * 32 + lane]);
        acc.x += nw * vv.x;
        acc.y += nw * vv.y;
        acc.z += nw * vv.z;
        acc.w += nw * vv.w;
    }
    float4 b = ((const float4*)bias)[lane];
    acc.x += b.x; acc.y += b.y; acc.z += b.z; acc.w += b.w;
    if (do_relu) {
        acc.x = fmaxf(acc.x, 0.f);
        acc.y = fmaxf(acc.y, 0.f);
        acc.z = fmaxf(acc.z, 0.f);
        acc.w = fmaxf(acc.w, 0.f);
    }
    __half2 o[2];
    o[0] = __floats2half2_rn(acc.x, acc.y);
    o[1] = __floats2half2_rn(acc.z, acc.w);
    *(uint2*)&g_a16[gw * 128 + lane * 4] = *(uint2*)o;
}

// ---------------- layer 3 aggregation (F=40, fp32 h stride 64) + softmax ----
__global__ void agg40_softmax_kernel(const float* __restrict__ b3,
                                     float* __restrict__ out, int n) {
    int gw = (blockIdx.x * blockDim.x + threadIdx.x) >> 5;
    if (gw >= n) return;
    int lane = threadIdx.x & 31;
    bool act = lane < 20;
    const float2* __restrict__ hv = (const float2*)g_h;

    float dd = g_dinv[gw];
    float ws = dd * dd;
    float2 acc = make_float2(0.f, 0.f);
    if (act) {
        float2 v = hv[gw * 32 + lane];
        acc.x = v.x * ws;
        acc.y = v.y * ws;
    }
    int beg = g_rowptr[gw];
    int end = g_rowptr[gw + 1];
    int i = beg;
    for (; i + 1 < end; i += 2) {
        int s0 = g_srcidx[i], s1 = g_srcidx[i + 1];
        float n0 = g_dinv[s0] * dd, n1 = g_dinv[s1] * dd;
        if (act) {
            float2 v0 = hv[s0 * 32 + lane];
            float2 v1 = hv[s1 * 32 + lane];
            acc.x += n0 * v0.x + n1 * v1.x;
            acc.y += n0 * v0.y + n1 * v1.y;
        }
    }
    if (i < end) {
        int s = g_srcidx[i];
        float nw = g_dinv[s] * dd;
        if (act) {
            float2 v = hv[s * 32 + lane];
            acc.x += nw * v.x;
            acc.y += nw * v.y;
        }
    }
    if (act) {
        acc.x += b3[lane * 2];
        acc.y += b3[lane * 2 + 1];
    }
    float m = act ? fmaxf(acc.x, acc.y) : -INFINITY;
#pragma unroll
    for (int off = 16; off > 0; off >>= 1) m = fmaxf(m, __shfl_xor_sync(0xFFFFFFFFu, m, off));
    float se = act ? (expf(acc.x - m) + expf(acc.y - m)) : 0.f;
#pragma unroll
    for (int off = 16; off > 0; off >>= 1) se += __shfl_xor_sync(0xFFFFFFFFu, se, off);
    float ls = m + logf(se);
    if (act) {
        out[gw * 40 + lane * 2 + 0] = acc.x - ls;
        out[gw * 40 + lane * 2 + 1] = acc.y - ls;
    }
}

// ---------------- launch -----------------------------------------------------
extern "C" void kernel_launch(void* const* d_in, const int* in_sizes, int n_in,
                              void* d_out, int out_size) {
    const float* x = (const float*)d_in[0];
    const int* ei = (const int*)d_in[1];
    const float* W1 = (const float*)d_in[2];
    const float* b1 = (const float*)d_in[3];
    const float* W2 = (const float*)d_in[4];
    const float* b2 = (const float*)d_in[5];
    const float* W3 = (const float*)d_in[6];
    const float* b3 = (const float*)d_in[7];
    float* out = (float*)d_out;

    const int n = in_sizes[0] / 128;   // 50000
    const int ne = in_sizes[1] / 2;    // 1600000

    int nb = (n + 255) / 256;
    int eb = (ne + 255) / 256;
    int wb = (n + 7) / 8;
    int sb = (n + SCAN_TILE - 1) / SCAN_TILE;
    int gb = (n + 127) / 128;

    const int SMEM_128 = (128 + 128) * 136 * 2;  // 69632
    const int SMEM_64  = (128 + 64) * 136 * 2;   // 52224
    cudaFuncSetAttribute((const void*)gemm_hmma<128, true, 1, true>,
                         cudaFuncAttributeMaxDynamicSharedMemorySize, SMEM_128);
    cudaFuncSetAttribute((const void*)gemm_hmma<128, false, 2, true>,
                         cudaFuncAttributeMaxDynamicSharedMemorySize, SMEM_128);
    cudaFuncSetAttribute((const void*)gemm_hmma<64, false, 3, false>,
                         cudaFuncAttributeMaxDynamicSharedMemorySize, SMEM_64);

    // preprocessing; layer-1 GEMM at 4th slot (profiler captures launch #4)
    zero_cnt_kernel<<<nb, 256>>>(n);
    x16_kernel<<<(n * 16 + 255) / 256, 256>>>(x, n * 16);
    w128t_kernel<1><<<64, 256>>>(W1);
    gemm_hmma<128, true, 1, true><<<gb, 256, SMEM_128>>>(n, 128);
    hist_kernel<<<eb, 256>>>(ei, ne);
    dinv_kernel<<<nb, 256>>>(n);
    scan_pass1<<<sb, SCAN_TILE>>>(n);
    scan_pass2<<<1, SCAN_TILE>>>(sb, n);
    scan_pass3<<<sb, SCAN_TILE>>>(n);
    fill_kernel<<<eb, 256>>>(ei, ne);
    w128t_kernel<2><<<64, 256>>>(W2);
    w3t_kernel<<<32, 256>>>(W3);

    // layer 1 aggregation (fp16 h -> fp16 a)
    agg128_kernel<<<wb, 256>>>(b1, n, 1);
    // layer 2
    gemm_hmma<128, false, 2, true><<<gb, 256, SMEM_128>>>(n, 128);
    agg128_kernel<<<wb, 256>>>(b2, n, 1);
    // layer 3 (fp32 out, stride 64, N padded 40 -> 64)
    gemm_hmma<64, false, 3, false><<<gb, 256, SMEM_64>>>(n, 64);
    agg40_softmax_kernel<<<wb, 256>>>(b3, out, n);
}

// round 11
// speedup vs baseline: 2.1477x; 1.0688x over previous
#include <cuda_runtime.h>
#include <cuda_bf16.h>
#include <cuda_fp16.h>
#include <math.h>

#define MAXN 50000
#define MAXE 1600000
#define SCAN_TILE 256
#define MAXB ((MAXN + SCAN_TILE - 1) / SCAN_TILE)

// ---------------- scratch ----------------------------------------------------
__device__ __align__(16) __half g_h16[MAXN * 128];  // fp16 GEMM out (L1/L2 stride 128, L3 stride 64)
__device__ __align__(16) __half g_a16[MAXN * 128];  // fp16 aggregation outputs
__device__ __align__(16) __half g_x16[MAXN * 128];  // fp16 copy of x
__device__ __align__(16) __half g_w1t[128 * 128];   // W1^T fp16 [n][k]
__device__ __align__(16) __half g_w2t[128 * 128];   // W2^T fp16 [n][k]
__device__ __align__(16) __half g_w3t[64 * 128];    // W3^T fp16 padded [n][k]
__device__ __align__(16) float  g_dinv[MAXN];
__device__ int   g_cnt[MAXN];
__device__ int   g_rowptr[MAXN + 1];
__device__ int   g_cursor[MAXN];
__device__ int   g_srcidx[MAXE];
__device__ int   g_bsum[MAXB];
__device__ int   g_boff[MAXB];

// ---------------- graph preprocessing ---------------------------------------
__global__ void zero_cnt_kernel(int n) {
    int i = blockIdx.x * blockDim.x + threadIdx.x;
    if (i < n) g_cnt[i] = 0;
}

__global__ void hist_kernel(const int* __restrict__ ei, int ne) {
    int e = blockIdx.x * blockDim.x + threadIdx.x;
    if (e < ne) {
        int d = ei[ne + e];
        atomicAdd(&g_cnt[d], 1);
    }
}

__global__ void dinv_kernel(int n) {
    int i = blockIdx.x * blockDim.x + threadIdx.x;
    if (i < n) g_dinv[i] = rsqrtf((float)(g_cnt[i] + 1));
}

__global__ void scan_pass1(int n) {
    __shared__ int sh[SCAN_TILE];
    int t = threadIdx.x;
    int i = blockIdx.x * SCAN_TILE + t;
    int v = (i < n) ? g_cnt[i] : 0;
    sh[t] = v;
    __syncthreads();
    for (int off = SCAN_TILE / 2; off > 0; off >>= 1) {
        if (t < off) sh[t] += sh[t + off];
        __syncthreads();
    }
    if (t == 0) g_bsum[blockIdx.x] = sh[0];
}

__global__ void scan_pass2(int nb, int n) {
    __shared__ int sh[SCAN_TILE];
    int t = threadIdx.x;
    int v = (t < nb) ? g_bsum[t] : 0;
    sh[t] = v;
    __syncthreads();
    for (int off = 1; off < SCAN_TILE; off <<= 1) {
        int u = (t >= off) ? sh[t - off] : 0;
        __syncthreads();
        sh[t] += u;
        __syncthreads();
    }
    if (t < nb) g_boff[t] = sh[t] - v;
    if (t == nb - 1) g_rowptr[n] = sh[t];
}

__global__ void scan_pass3(int n) {
    __shared__ int sh[SCAN_TILE];
    int t = threadIdx.x;
    int i = blockIdx.x * SCAN_TILE + t;
    int v = (i < n) ? g_cnt[i] : 0;
    sh[t] = v;
    __syncthreads();
    for (int off = 1; off < SCAN_TILE; off <<= 1) {
        int u = (t >= off) ? sh[t - off] : 0;
        __syncthreads();
        sh[t] += u;
        __syncthreads();
    }
    if (i < n) {
        int excl = g_boff[blockIdx.x] + sh[t] - v;
        g_rowptr[i] = excl;
        g_cursor[i] = excl;
    }
}

__global__ void fill_kernel(const int* __restrict__ ei, int ne) {
    int e = blockIdx.x * blockDim.x + threadIdx.x;
    if (e < ne) {
        int s = ei[e];
        int d = ei[ne + e];
        int pos = atomicAdd(&g_cursor[d], 1);
        g_srcidx[pos] = s;
    }
}

// x (fp32) -> g_x16 (fp16), 8 elems per thread
__global__ void x16_kernel(const float* __restrict__ x, int total8) {
    int i = blockIdx.x * blockDim.x + threadIdx.x;
    if (i < total8) {
        float4 v0 = *(const float4*)&x[i * 8];
        float4 v1 = *(const float4*)&x[i * 8 + 4];
        __half2 h[4];
        h[0] = __floats2half2_rn(v0.x, v0.y);
        h[1] = __floats2half2_rn(v0.z, v0.w);
        h[2] = __floats2half2_rn(v1.x, v1.y);
        h[3] = __floats2half2_rn(v1.z, v1.w);
        *(uint4*)&g_x16[i * 8] = *(uint4*)h;
    }
}

// W[128 x 128] fp32 -> transposed fp16 [n][k]; destination symbol chosen in
// device code (GB300/ATS: host-shadow of a __device__ symbol is silently
// dereferenceable — never pass the symbol as a host-side kernel arg).
template <int WSEL>
__global__ void w128t_kernel(const float* __restrict__ W) {
    __half* out = (WSEL == 1) ? g_w1t : g_w2t;
    int i = blockIdx.x * blockDim.x + threadIdx.x;  // 16384
    int nn = i >> 7, k = i & 127;
    out[i] = __float2half(W[k * 128 + nn]);
}

// W3[128 x 40] fp32 -> transposed fp16 padded [64][128]
__global__ void w3t_kernel(const float* __restrict__ W3) {
    int i = blockIdx.x * blockDim.x + threadIdx.x;  // 8192
    int nn = i >> 7, k = i & 127;
    g_w3t[i] = (nn < 40) ? __float2half(W3[k * 40 + nn]) : __half(0.f);
}

// ---------------- HMMA GEMM: C = A[M x 128](fp16) @ B[128 x BN] -------------
__device__ __forceinline__ void mma16816(float* c, const unsigned* a, const unsigned* b) {
    asm volatile(
        "mma.sync.aligned.m16n8k16.row.col.f32.f16.f16.f32 "
        "{%0,%1,%2,%3}, {%4,%5,%6,%7}, {%8,%9}, {%0,%1,%2,%3};"
        : "+f"(c[0]), "+f"(c[1]), "+f"(c[2]), "+f"(c[3])
        : "r"(a[0]), "r"(a[1]), "r"(a[2]), "r"(a[3]), "r"(b[0]), "r"(b[1]));
}

template <int BN, bool A_IS_X, int WSEL>
__global__ void gemm_hmma(int M, int ldc) {
    constexpr int LDA = 136;
    constexpr int WARPS_N = BN / 32;
    constexpr int WARPS_M = 8 / WARPS_N;
    constexpr int MT = (128 / WARPS_M) / 16;

    extern __shared__ __half smem[];
    __half* As = smem;                  // [128][LDA]
    __half* Bs = smem + 128 * LDA;      // [BN][LDA]

    const __half* __restrict__ A = A_IS_X ? (const __half*)g_x16 : (const __half*)g_a16;
    const __half* __restrict__ Bt =
        (WSEL == 1) ? (const __half*)g_w1t :
        (WSEL == 2) ? (const __half*)g_w2t : (const __half*)g_w3t;

    int tid = threadIdx.x;
    int rowBase = blockIdx.x * 128;

#pragma unroll
    for (int l = 0; l < 8; l++) {
        int idx = tid + l * 256;
        int r = idx >> 4;
        int c = (idx & 15) * 8;
        uint4 v = make_uint4(0, 0, 0, 0);
        int grow = rowBase + r;
        if (grow < M) v = *(const uint4*)&A[grow * 128 + c];
        *(uint4*)&As[r * LDA + c] = v;
    }
#pragma unroll
    for (int l = 0; l < BN / 16; l++) {
        int idx = tid + l * 256;
        int r = idx >> 4;
        int c = (idx & 15) * 8;
        *(uint4*)&Bs[r * LDA + c] = *(const uint4*)&Bt[r * 128 + c];
    }
    __syncthreads();

    int wid = tid >> 5, lane = tid & 31;
    int g = lane >> 2, t = lane & 3;
    int wm = (wid / WARPS_N) * (MT * 16);
    int wn = (wid % WARPS_N) * 32;

    float acc[MT][4][4];
#pragma unroll
    for (int mi = 0; mi < MT; mi++)
#pragma unroll
        for (int ni = 0; ni < 4; ni++)
#pragma unroll
            for (int q = 0; q < 4; q++) acc[mi][ni][q] = 0.f;

#pragma unroll
    for (int ks = 0; ks < 8; ks++) {
        int k0 = ks * 16;
        unsigned afr[MT][4], bfr[4][2];
#pragma unroll
        for (int mi = 0; mi < MT; mi++) {
            const __half* base = &As[(wm + mi * 16 + g) * LDA + k0 + 2 * t];
            afr[mi][0] = *(const unsigned*)(base);
            afr[mi][1] = *(const unsigned*)(base + 8 * LDA);
            afr[mi][2] = *(const unsigned*)(base + 8);
            afr[mi][3] = *(const unsigned*)(base + 8 * LDA + 8);
        }
#pragma unroll
        for (int ni = 0; ni < 4; ni++) {
            const __half* bb = &Bs[(wn + ni * 8 + g) * LDA + k0 + 2 * t];
            bfr[ni][0] = *(const unsigned*)(bb);
            bfr[ni][1] = *(const unsigned*)(bb + 8);
        }
#pragma unroll
        for (int mi = 0; mi < MT; mi++)
#pragma unroll
            for (int ni = 0; ni < 4; ni++)
                mma16816(acc[mi][ni], afr[mi], bfr[ni]);
    }

#pragma unroll
    for (int mi = 0; mi < MT; mi++) {
#pragma unroll
        for (int ni = 0; ni < 4; ni++) {
            int r0 = rowBase + wm + mi * 16 + g;
            int c = wn + ni * 8 + 2 * t;
            if (r0 < M) {
                __half2 h = __floats2half2_rn(acc[mi][ni][0], acc[mi][ni][1]);
                *(__half2*)&g_h16[r0 * ldc + c] = h;
            }
            if (r0 + 8 < M) {
                __half2 h = __floats2half2_rn(acc[mi][ni][2], acc[mi][ni][3]);
                *(__half2*)&g_h16[(r0 + 8) * ldc + c] = h;
            }
        }
    }
}

// ---------------- aggregation (F=128), warp per node, split-lane uint4 ------
// lanes 0-15 and 16-31 process two edges at once: each lane loads one uint4
// (8 halfs) of its edge's row; halves are combined via shfl_xor(16).
__device__ __forceinline__ void cvt8(uint4 r, float* f) {
    __half2* p = (__half2*)&r;
    float2 a = __half22float2(p[0]);
    float2 b = __half22float2(p[1]);
    float2 c = __half22float2(p[2]);
    float2 d = __half22float2(p[3]);
    f[0] = a.x; f[1] = a.y; f[2] = b.x; f[3] = b.y;
    f[4] = c.x; f[5] = c.y; f[6] = d.x; f[7] = d.y;
}

__global__ void agg128_kernel(const float* __restrict__ bias, int n, int do_relu) {
    int gw = (blockIdx.x * blockDim.x + threadIdx.x) >> 5;
    if (gw >= n) return;
    int lane = threadIdx.x & 31;
    int hf = lane >> 4;        // 0/1: which edge of the pair
    int sub = lane & 15;       // 16B chunk within the 256B row
    const uint4* __restrict__ hv = (const uint4*)g_h16;  // row = 16 uint4

    float dd = g_dinv[gw];
    float acc[8];
    {   // self-loop: both halves contribute ws/2 (sums exactly in fp32)
        float ws2 = dd * dd * 0.5f;
        float f[8];
        cvt8(hv[gw * 16 + sub], f);
#pragma unroll
        for (int q = 0; q < 8; q++) acc[q] = f[q] * ws2;
    }

    int beg = g_rowptr[gw];
    int end = g_rowptr[gw + 1];
    int i = beg;
    // 4 edges per iteration: two uint4 loads in flight per lane
    for (; i + 3 < end; i += 4) {
        int s0 = g_srcidx[i], s1 = g_srcidx[i + 1];
        int s2 = g_srcidx[i + 2], s3 = g_srcidx[i + 3];
        int sa = hf ? s1 : s0;
        int sb = hf ? s3 : s2;
        float wa = g_dinv[sa] * dd;
        float wb = g_dinv[sb] * dd;
        uint4 ra = hv[sa * 16 + sub];
        uint4 rb = hv[sb * 16 + sub];
        float fa[8], fb[8];
        cvt8(ra, fa);
        cvt8(rb, fb);
#pragma unroll
        for (int q = 0; q < 8; q++) acc[q] += wa * fa[q] + wb * fb[q];
    }
    for (; i + 1 < end; i += 2) {
        int s0 = g_srcidx[i], s1 = g_srcidx[i + 1];
        int sa = hf ? s1 : s0;
        float wa = g_dinv[sa] * dd;
        uint4 ra = hv[sa * 16 + sub];
        float fa[8];
        cvt8(ra, fa);
#pragma unroll
        for (int q = 0; q < 8; q++) acc[q] += wa * fa[q];
    }
    if (i < end) {  // odd remainder: half 1 contributes zero
        int s0 = g_srcidx[i];
        float wa = hf ? 0.f : g_dinv[s0] * dd;
        uint4 ra = hv[s0 * 16 + sub];
        float fa[8];
        cvt8(ra, fa);
#pragma unroll
        for (int q = 0; q < 8; q++) acc[q] += wa * fa[q];
    }
    // combine halves
#pragma unroll
    for (int q = 0; q < 8; q++) acc[q] += __shfl_xor_sync(0xFFFFFFFFu, acc[q], 16);

    float4 b0 = ((const float4*)bias)[sub * 2];
    float4 b1 = ((const float4*)bias)[sub * 2 + 1];
    acc[0] += b0.x; acc[1] += b0.y; acc[2] += b0.z; acc[3] += b0.w;
    acc[4] += b1.x; acc[5] += b1.y; acc[6] += b1.z; acc[7] += b1.w;
    if (do_relu) {
#pragma unroll
        for (int q = 0; q < 8; q++) acc[q] = fmaxf(acc[q], 0.f);
    }
    if (hf == 0) {
        __half2 o[4];
        o[0] = __floats2half2_rn(acc[0], acc[1]);
        o[1] = __floats2half2_rn(acc[2], acc[3]);
        o[2] = __floats2half2_rn(acc[4], acc[5]);
        o[3] = __floats2half2_rn(acc[6], acc[7]);
        *(uint4*)&g_a16[gw * 128 + sub * 8] = *(uint4*)o;
    }
}

// ---------------- layer 3 aggregation (F=40, fp16 h stride 64) + softmax ----
__global__ void agg40_softmax_kernel(const float* __restrict__ b3,
                                     float* __restrict__ out, int n) {
    int gw = (blockIdx.x * blockDim.x + threadIdx.x) >> 5;
    if (gw >= n) return;
    int lane = threadIdx.x & 31;
    bool act = lane < 20;
    const __half2* __restrict__ hv = (const __half2*)g_h16;  // row stride = 32 half2

    float dd = g_dinv[gw];
    float ws = dd * dd;
    float2 acc = make_float2(0.f, 0.f);
    if (act) {
        float2 v = __half22float2(hv[gw * 32 + lane]);
        acc.x = v.x * ws;
        acc.y = v.y * ws;
    }
    int beg = g_rowptr[gw];
    int end = g_rowptr[gw + 1];
    int i = beg;
    for (; i + 1 < end; i += 2) {
        int s0 = g_srcidx[i], s1 = g_srcidx[i + 1];
        float n0 = g_dinv[s0] * dd, n1 = g_dinv[s1] * dd;
        if (act) {
            float2 v0 = __half22float2(hv[s0 * 32 + lane]);
            float2 v1 = __half22float2(hv[s1 * 32 + lane]);
            acc.x += n0 * v0.x + n1 * v1.x;
            acc.y += n0 * v0.y + n1 * v1.y;
        }
    }
    if (i < end) {
        int s = g_srcidx[i];
        float nw = g_dinv[s] * dd;
        if (act) {
            float2 v = __half22float2(hv[s * 32 + lane]);
            acc.x += nw * v.x;
            acc.y += nw * v.y;
        }
    }
    if (act) {
        acc.x += b3[lane * 2];
        acc.y += b3[lane * 2 + 1];
    }
    float m = act ? fmaxf(acc.x, acc.y) : -INFINITY;
#pragma unroll
    for (int off = 16; off > 0; off >>= 1) m = fmaxf(m, __shfl_xor_sync(0xFFFFFFFFu, m, off));
    float se = act ? (expf(acc.x - m) + expf(acc.y - m)) : 0.f;
#pragma unroll
    for (int off = 16; off > 0; off >>= 1) se += __shfl_xor_sync(0xFFFFFFFFu, se, off);
    float ls = m + logf(se);
    if (act) {
        out[gw * 40 + lane * 2 + 0] = acc.x - ls;
        out[gw * 40 + lane * 2 + 1] = acc.y - ls;
    }
}

// ---------------- launch -----------------------------------------------------
extern "C" void kernel_launch(void* const* d_in, const int* in_sizes, int n_in,
                              void* d_out, int out_size) {
    const float* x = (const float*)d_in[0];
    const int* ei = (const int*)d_in[1];
    const float* W1 = (const float*)d_in[2];
    const float* b1 = (const float*)d_in[3];
    const float* W2 = (const float*)d_in[4];
    const float* b2 = (const float*)d_in[5];
    const float* W3 = (const float*)d_in[6];
    const float* b3 = (const float*)d_in[7];
    float* out = (float*)d_out;

    const int n = in_sizes[0] / 128;   // 50000
    const int ne = in_sizes[1] / 2;    // 1600000

    int nb = (n + 255) / 256;
    int eb = (ne + 255) / 256;
    int wb = (n + 7) / 8;
    int sb = (n + SCAN_TILE - 1) / SCAN_TILE;
    int gb = (n + 127) / 128;

    const int SMEM_128 = (128 + 128) * 136 * 2;  // 69632
    const int SMEM_64  = (128 + 64) * 136 * 2;   // 52224
    cudaFuncSetAttribute((const void*)gemm_hmma<128, true, 1>,
                         cudaFuncAttributeMaxDynamicSharedMemorySize, SMEM_128);
    cudaFuncSetAttribute((const void*)gemm_hmma<128, false, 2>,
                         cudaFuncAttributeMaxDynamicSharedMemorySize, SMEM_128);
    cudaFuncSetAttribute((const void*)gemm_hmma<64, false, 3>,
                         cudaFuncAttributeMaxDynamicSharedMemorySize, SMEM_64);

    // preprocessing; layer-1 agg placed later; 4th launch = gemm (profiler slot)
    zero_cnt_kernel<<<nb, 256>>>(n);
    x16_kernel<<<(n * 16 + 255) / 256, 256>>>(x, n * 16);
    w128t_kernel<1><<<64, 256>>>(W1);
    gemm_hmma<128, true, 1><<<gb, 256, SMEM_128>>>(n, 128);
    hist_kernel<<<eb, 256>>>(ei, ne);
    dinv_kernel<<<nb, 256>>>(n);
    scan_pass1<<<sb, SCAN_TILE>>>(n);
    scan_pass2<<<1, SCAN_TILE>>>(sb, n);
    scan_pass3<<<sb, SCAN_TILE>>>(n);
    fill_kernel<<<eb, 256>>>(ei, ne);
    w128t_kernel<2><<<64, 256>>>(W2);
    w3t_kernel<<<32, 256>>>(W3);

    // layer 1 aggregation (fp16 h -> fp16 a)
    agg128_kernel<<<wb, 256>>>(b1, n, 1);
    // layer 2
    gemm_hmma<128, false, 2><<<gb, 256, SMEM_128>>>(n, 128);
    agg128_kernel<<<wb, 256>>>(b2, n, 1);
    // layer 3 (fp16 out, stride 64, N padded 40 -> 64)
    gemm_hmma<64, false, 3><<<gb, 256, SMEM_64>>>(n, 64);
    agg40_softmax_kernel<<<wb, 256>>>(b3, out, n);
}

// round 12
// speedup vs baseline: 2.3847x; 1.1104x over previous
#include <cuda_runtime.h>
#include <cuda_bf16.h>
#include <cuda_fp16.h>
#include <math.h>

#define MAXN 50000
#define MAXE 1600000
#define SCAN_TILE 256
#define MAXB ((MAXN + SCAN_TILE - 1) / SCAN_TILE)

// ---------------- scratch ----------------------------------------------------
__device__ __align__(16) __half g_h16[MAXN * 128];  // fp16 GEMM out, pre-scaled by dinv[row]
__device__ __align__(16) __half g_a16[MAXN * 128];  // fp16 aggregation outputs
__device__ __align__(16) __half g_x16[MAXN * 128];  // fp16 copy of x
__device__ __align__(16) __half g_w1t[128 * 128];   // W1^T fp16 [n][k]
__device__ __align__(16) __half g_w2t[128 * 128];   // W2^T fp16 [n][k]
__device__ __align__(16) __half g_w3t[64 * 128];    // W3^T fp16 padded [n][k]
__device__ __align__(16) float  g_dinv[MAXN];
__device__ int   g_cnt[MAXN];
__device__ int   g_rowptr[MAXN + 1];
__device__ int   g_cursor[MAXN];
__device__ int   g_srcidx[MAXE];
__device__ int   g_bsum[MAXB];
__device__ int   g_boff[MAXB];

// ---------------- graph preprocessing ---------------------------------------
__global__ void zero_cnt_kernel(int n) {
    int i = blockIdx.x * blockDim.x + threadIdx.x;
    if (i < n) g_cnt[i] = 0;
}

__global__ void hist_kernel(const int* __restrict__ ei, int ne) {
    int e = blockIdx.x * blockDim.x + threadIdx.x;
    if (e < ne) {
        int d = ei[ne + e];
        atomicAdd(&g_cnt[d], 1);
    }
}

__global__ void dinv_kernel(int n) {
    int i = blockIdx.x * blockDim.x + threadIdx.x;
    if (i < n) g_dinv[i] = rsqrtf((float)(g_cnt[i] + 1));
}

__global__ void scan_pass1(int n) {
    __shared__ int sh[SCAN_TILE];
    int t = threadIdx.x;
    int i = blockIdx.x * SCAN_TILE + t;
    int v = (i < n) ? g_cnt[i] : 0;
    sh[t] = v;
    __syncthreads();
    for (int off = SCAN_TILE / 2; off > 0; off >>= 1) {
        if (t < off) sh[t] += sh[t + off];
        __syncthreads();
    }
    if (t == 0) g_bsum[blockIdx.x] = sh[0];
}

__global__ void scan_pass2(int nb, int n) {
    __shared__ int sh[SCAN_TILE];
    int t = threadIdx.x;
    int v = (t < nb) ? g_bsum[t] : 0;
    sh[t] = v;
    __syncthreads();
    for (int off = 1; off < SCAN_TILE; off <<= 1) {
        int u = (t >= off) ? sh[t - off] : 0;
        __syncthreads();
        sh[t] += u;
        __syncthreads();
    }
    if (t < nb) g_boff[t] = sh[t] - v;
    if (t == nb - 1) g_rowptr[n] = sh[t];
}

__global__ void scan_pass3(int n) {
    __shared__ int sh[SCAN_TILE];
    int t = threadIdx.x;
    int i = blockIdx.x * SCAN_TILE + t;
    int v = (i < n) ? g_cnt[i] : 0;
    sh[t] = v;
    __syncthreads();
    for (int off = 1; off < SCAN_TILE; off <<= 1) {
        int u = (t >= off) ? sh[t - off] : 0;
        __syncthreads();
        sh[t] += u;
        __syncthreads();
    }
    if (i < n) {
        int excl = g_boff[blockIdx.x] + sh[t] - v;
        g_rowptr[i] = excl;
        g_cursor[i] = excl;
    }
}

__global__ void fill_kernel(const int* __restrict__ ei, int ne) {
    int e = blockIdx.x * blockDim.x + threadIdx.x;
    if (e < ne) {
        int s = ei[e];
        int d = ei[ne + e];
        int pos = atomicAdd(&g_cursor[d], 1);
        g_srcidx[pos] = s;
    }
}

// x (fp32) -> g_x16 (fp16)
__global__ void x16_kernel(const float* __restrict__ x, int total8) {
    int i = blockIdx.x * blockDim.x + threadIdx.x;
    if (i < total8) {
        float4 v0 = *(const float4*)&x[i * 8];
        float4 v1 = *(const float4*)&x[i * 8 + 4];
        __half2 h[4];
        h[0] = __floats2half2_rn(v0.x, v0.y);
        h[1] = __floats2half2_rn(v0.z, v0.w);
        h[2] = __floats2half2_rn(v1.x, v1.y);
        h[3] = __floats2half2_rn(v1.z, v1.w);
        *(uint4*)&g_x16[i * 8] = *(uint4*)h;
    }
}

// W[128 x 128] fp32 -> transposed fp16 [n][k]; destination symbol chosen in
// device code (GB300/ATS pitfall: never pass a __device__ symbol host-side).
template <int WSEL>
__global__ void w128t_kernel(const float* __restrict__ W) {
    __half* out = (WSEL == 1) ? g_w1t : g_w2t;
    int i = blockIdx.x * blockDim.x + threadIdx.x;  // 16384
    int nn = i >> 7, k = i & 127;
    out[i] = __float2half(W[k * 128 + nn]);
}

__global__ void w3t_kernel(const float* __restrict__ W3) {
    int i = blockIdx.x * blockDim.x + threadIdx.x;  // 8192
    int nn = i >> 7, k = i & 127;
    g_w3t[i] = (nn < 40) ? __float2half(W3[k * 40 + nn]) : __half(0.f);
}

// ---------------- HMMA GEMM: h' = (A @ B) * dinv[row], fp16 out -------------
__device__ __forceinline__ void mma16816(float* c, const unsigned* a, const unsigned* b) {
    asm volatile(
        "mma.sync.aligned.m16n8k16.row.col.f32.f16.f16.f32 "
        "{%0,%1,%2,%3}, {%4,%5,%6,%7}, {%8,%9}, {%0,%1,%2,%3};"
        : "+f"(c[0]), "+f"(c[1]), "+f"(c[2]), "+f"(c[3])
        : "r"(a[0]), "r"(a[1]), "r"(a[2]), "r"(a[3]), "r"(b[0]), "r"(b[1]));
}

template <int BN, bool A_IS_X, int WSEL>
__global__ void gemm_hmma(int M, int ldc) {
    constexpr int LDA = 136;
    constexpr int WARPS_N = BN / 32;
    constexpr int WARPS_M = 8 / WARPS_N;
    constexpr int MT = (128 / WARPS_M) / 16;

    extern __shared__ __half smem[];
    __half* As = smem;                  // [128][LDA]
    __half* Bs = smem + 128 * LDA;      // [BN][LDA]

    const __half* __restrict__ A = A_IS_X ? (const __half*)g_x16 : (const __half*)g_a16;
    const __half* __restrict__ Bt =
        (WSEL == 1) ? (const __half*)g_w1t :
        (WSEL == 2) ? (const __half*)g_w2t : (const __half*)g_w3t;

    int tid = threadIdx.x;
    int rowBase = blockIdx.x * 128;

#pragma unroll
    for (int l = 0; l < 8; l++) {
        int idx = tid + l * 256;
        int r = idx >> 4;
        int c = (idx & 15) * 8;
        uint4 v = make_uint4(0, 0, 0, 0);
        int grow = rowBase + r;
        if (grow < M) v = *(const uint4*)&A[grow * 128 + c];
        *(uint4*)&As[r * LDA + c] = v;
    }
#pragma unroll
    for (int l = 0; l < BN / 16; l++) {
        int idx = tid + l * 256;
        int r = idx >> 4;
        int c = (idx & 15) * 8;
        *(uint4*)&Bs[r * LDA + c] = *(const uint4*)&Bt[r * 128 + c];
    }
    __syncthreads();

    int wid = tid >> 5, lane = tid & 31;
    int g = lane >> 2, t = lane & 3;
    int wm = (wid / WARPS_N) * (MT * 16);
    int wn = (wid % WARPS_N) * 32;

    float acc[MT][4][4];
#pragma unroll
    for (int mi = 0; mi < MT; mi++)
#pragma unroll
        for (int ni = 0; ni < 4; ni++)
#pragma unroll
            for (int q = 0; q < 4; q++) acc[mi][ni][q] = 0.f;

#pragma unroll
    for (int ks = 0; ks < 8; ks++) {
        int k0 = ks * 16;
        unsigned afr[MT][4], bfr[4][2];
#pragma unroll
        for (int mi = 0; mi < MT; mi++) {
            const __half* base = &As[(wm + mi * 16 + g) * LDA + k0 + 2 * t];
            afr[mi][0] = *(const unsigned*)(base);
            afr[mi][1] = *(const unsigned*)(base + 8 * LDA);
            afr[mi][2] = *(const unsigned*)(base + 8);
            afr[mi][3] = *(const unsigned*)(base + 8 * LDA + 8);
        }
#pragma unroll
        for (int ni = 0; ni < 4; ni++) {
            const __half* bb = &Bs[(wn + ni * 8 + g) * LDA + k0 + 2 * t];
            bfr[ni][0] = *(const unsigned*)(bb);
            bfr[ni][1] = *(const unsigned*)(bb + 8);
        }
#pragma unroll
        for (int mi = 0; mi < MT; mi++)
#pragma unroll
            for (int ni = 0; ni < 4; ni++)
                mma16816(acc[mi][ni], afr[mi], bfr[ni]);
    }

    // epilogue: scale each row by dinv[row], store fp16
#pragma unroll
    for (int mi = 0; mi < MT; mi++) {
        int r0 = rowBase + wm + mi * 16 + g;
        float s0 = (r0 < M) ? g_dinv[r0] : 0.f;
        float s1 = (r0 + 8 < M) ? g_dinv[r0 + 8] : 0.f;
#pragma unroll
        for (int ni = 0; ni < 4; ni++) {
            int c = wn + ni * 8 + 2 * t;
            if (r0 < M) {
                __half2 h = __floats2half2_rn(acc[mi][ni][0] * s0, acc[mi][ni][1] * s0);
                *(__half2*)&g_h16[r0 * ldc + c] = h;
            }
            if (r0 + 8 < M) {
                __half2 h = __floats2half2_rn(acc[mi][ni][2] * s1, acc[mi][ni][3] * s1);
                *(__half2*)&g_h16[(r0 + 8) * ldc + c] = h;
            }
        }
    }
}

// ---------------- aggregation (F=128), warp/node, pure row sum --------------
// h' rows are pre-scaled by dinv[src]; out = relu(dinv[d]*(sum + self) + bias)
__device__ __forceinline__ void cvt8(uint4 r, float* f) {
    __half2* p = (__half2*)&r;
    float2 a = __half22float2(p[0]);
    float2 b = __half22float2(p[1]);
    float2 c = __half22float2(p[2]);
    float2 d = __half22float2(p[3]);
    f[0] = a.x; f[1] = a.y; f[2] = b.x; f[3] = b.y;
    f[4] = c.x; f[5] = c.y; f[6] = d.x; f[7] = d.y;
}

__global__ void agg128_kernel(const float* __restrict__ bias, int n, int do_relu) {
    int gw = (blockIdx.x * blockDim.x + threadIdx.x) >> 5;
    if (gw >= n) return;
    int lane = threadIdx.x & 31;
    int hf = lane >> 4;        // which edge of the pair
    int sub = lane & 15;       // 16B chunk within the 256B row
    const uint4* __restrict__ hv = (const uint4*)g_h16;

    float acc[8];
    {   // self-loop h'[d]: each half adds 0.5x (exact after combine)
        float f[8];
        cvt8(hv[gw * 16 + sub], f);
#pragma unroll
        for (int q = 0; q < 8; q++) acc[q] = 0.5f * f[q];
    }

    int beg = g_rowptr[gw];
    int end = g_rowptr[gw + 1];
    int i = beg;
    for (; i + 3 < end; i += 4) {
        int s0 = g_srcidx[i], s1 = g_srcidx[i + 1];
        int s2 = g_srcidx[i + 2], s3 = g_srcidx[i + 3];
        int sa = hf ? s1 : s0;
        int sb = hf ? s3 : s2;
        uint4 ra = hv[sa * 16 + sub];
        uint4 rb = hv[sb * 16 + sub];
        float fa[8], fb[8];
        cvt8(ra, fa);
        cvt8(rb, fb);
#pragma unroll
        for (int q = 0; q < 8; q++) acc[q] += fa[q] + fb[q];
    }
    for (; i + 1 < end; i += 2) {
        int s0 = g_srcidx[i], s1 = g_srcidx[i + 1];
        int sa = hf ? s1 : s0;
        uint4 ra = hv[sa * 16 + sub];
        float fa[8];
        cvt8(ra, fa);
#pragma unroll
        for (int q = 0; q < 8; q++) acc[q] += fa[q];
    }
    if (i < end) {  // odd remainder: half 1 contributes 0
        int s0 = g_srcidx[i];
        float w = hf ? 0.f : 1.f;
        uint4 ra = hv[s0 * 16 + sub];
        float fa[8];
        cvt8(ra, fa);
#pragma unroll
        for (int q = 0; q < 8; q++) acc[q] += w * fa[q];
    }
#pragma unroll
    for (int q = 0; q < 8; q++) acc[q] += __shfl_xor_sync(0xFFFFFFFFu, acc[q], 16);

    float dd = g_dinv[gw];
    float4 b0 = ((const float4*)bias)[sub * 2];
    float4 b1 = ((const float4*)bias)[sub * 2 + 1];
    acc[0] = acc[0] * dd + b0.x; acc[1] = acc[1] * dd + b0.y;
    acc[2] = acc[2] * dd + b0.z; acc[3] = acc[3] * dd + b0.w;
    acc[4] = acc[4] * dd + b1.x; acc[5] = acc[5] * dd + b1.y;
    acc[6] = acc[6] * dd + b1.z; acc[7] = acc[7] * dd + b1.w;
    if (do_relu) {
#pragma unroll
        for (int q = 0; q < 8; q++) acc[q] = fmaxf(acc[q], 0.f);
    }
    if (hf == 0) {
        __half2 o[4];
        o[0] = __floats2half2_rn(acc[0], acc[1]);
        o[1] = __floats2half2_rn(acc[2], acc[3]);
        o[2] = __floats2half2_rn(acc[4], acc[5]);
        o[3] = __floats2half2_rn(acc[6], acc[7]);
        *(uint4*)&g_a16[gw * 128 + sub * 8] = *(uint4*)o;
    }
}

// ---------------- layer 3 aggregation (F=40, fp16 h' stride 64) + softmax ---
__global__ void agg40_softmax_kernel(const float* __restrict__ b3,
                                     float* __restrict__ out, int n) {
    int gw = (blockIdx.x * blockDim.x + threadIdx.x) >> 5;
    if (gw >= n) return;
    int lane = threadIdx.x & 31;
    bool act = lane < 20;
    const __half2* __restrict__ hv = (const __half2*)g_h16;  // row stride = 32 half2

    float2 acc = make_float2(0.f, 0.f);
    if (act) {
        float2 v = __half22float2(hv[gw * 32 + lane]);  // self h'[d]
        acc.x = v.x;
        acc.y = v.y;
    }
    int beg = g_rowptr[gw];
    int end = g_rowptr[gw + 1];
    int i = beg;
    for (; i + 1 < end; i += 2) {
        int s0 = g_srcidx[i], s1 = g_srcidx[i + 1];
        if (act) {
            float2 v0 = __half22float2(hv[s0 * 32 + lane]);
            float2 v1 = __half22float2(hv[s1 * 32 + lane]);
            acc.x += v0.x + v1.x;
            acc.y += v0.y + v1.y;
        }
    }
    if (i < end) {
        int s = g_srcidx[i];
        if (act) {
            float2 v = __half22float2(hv[s * 32 + lane]);
            acc.x += v.x;
            acc.y += v.y;
        }
    }
    if (act) {
        float dd = g_dinv[gw];
        acc.x = acc.x * dd + b3[lane * 2];
        acc.y = acc.y * dd + b3[lane * 2 + 1];
    }
    float m = act ? fmaxf(acc.x, acc.y) : -INFINITY;
#pragma unroll
    for (int off = 16; off > 0; off >>= 1) m = fmaxf(m, __shfl_xor_sync(0xFFFFFFFFu, m, off));
    float se = act ? (expf(acc.x - m) + expf(acc.y - m)) : 0.f;
#pragma unroll
    for (int off = 16; off > 0; off >>= 1) se += __shfl_xor_sync(0xFFFFFFFFu, se, off);
    float ls = m + logf(se);
    if (act) {
        out[gw * 40 + lane * 2 + 0] = acc.x - ls;
        out[gw * 40 + lane * 2 + 1] = acc.y - ls;
    }
}

// ---------------- launch -----------------------------------------------------
extern "C" void kernel_launch(void* const* d_in, const int* in_sizes, int n_in,
                              void* d_out, int out_size) {
    const float* x = (const float*)d_in[0];
    const int* ei = (const int*)d_in[1];
    const float* W1 = (const float*)d_in[2];
    const float* b1 = (const float*)d_in[3];
    const float* W2 = (const float*)d_in[4];
    const float* b2 = (const float*)d_in[5];
    const float* W3 = (const float*)d_in[6];
    const float* b3 = (const float*)d_in[7];
    float* out = (float*)d_out;

    const int n = in_sizes[0] / 128;   // 50000
    const int ne = in_sizes[1] / 2;    // 1600000

    int nb = (n + 255) / 256;
    int eb = (ne + 255) / 256;
    int wb = (n + 7) / 8;
    int sb = (n + SCAN_TILE - 1) / SCAN_TILE;
    int gb = (n + 127) / 128;

    const int SMEM_128 = (128 + 128) * 136 * 2;  // 69632
    const int SMEM_64  = (128 + 64) * 136 * 2;   // 52224
    cudaFuncSetAttribute((const void*)gemm_hmma<128, true, 1>,
                         cudaFuncAttributeMaxDynamicSharedMemorySize, SMEM_128);
    cudaFuncSetAttribute((const void*)gemm_hmma<128, false, 2>,
                         cudaFuncAttributeMaxDynamicSharedMemorySize, SMEM_128);
    cudaFuncSetAttribute((const void*)gemm_hmma<64, false, 3>,
                         cudaFuncAttributeMaxDynamicSharedMemorySize, SMEM_64);

    // preprocessing (dinv must precede GEMMs: epilogue row-scaling)
    zero_cnt_kernel<<<nb, 256>>>(n);
    hist_kernel<<<eb, 256>>>(ei, ne);
    dinv_kernel<<<nb, 256>>>(n);
    x16_kernel<<<(n * 16 + 255) / 256, 256>>>(x, n * 16);
    w128t_kernel<1><<<64, 256>>>(W1);
    gemm_hmma<128, true, 1><<<gb, 256, SMEM_128>>>(n, 128);
    scan_pass1<<<sb, SCAN_TILE>>>(n);
    scan_pass2<<<1, SCAN_TILE>>>(sb, n);
    scan_pass3<<<sb, SCAN_TILE>>>(n);
    fill_kernel<<<eb, 256>>>(ei, ne);
    w128t_kernel<2><<<64, 256>>>(W2);
    w3t_kernel<<<32, 256>>>(W3);

    // layer 1 aggregation
    agg128_kernel<<<wb, 256>>>(b1, n, 1);
    // layer 2
    gemm_hmma<128, false, 2><<<gb, 256, SMEM_128>>>(n, 128);
    agg128_kernel<<<wb, 256>>>(b2, n, 1);
    // layer 3
    gemm_hmma<64, false, 3><<<gb, 256, SMEM_64>>>(n, 64);
    agg40_softmax_kernel<<<wb, 256>>>(b3, out, n);
}

// round 13
// speedup vs baseline: 2.4045x; 1.0083x over previous
#include <cuda_runtime.h>
#include <cuda_bf16.h>
#include <cuda_fp16.h>
#include <math.h>

#define MAXN 50000
#define MAXE 1600000
#define SCAN_TILE 256
#define MAXB ((MAXN + SCAN_TILE - 1) / SCAN_TILE)

// ---------------- scratch ----------------------------------------------------
__device__ __align__(16) __half g_h16[MAXN * 128];  // fp16 GEMM out, pre-scaled by dinv[row]
__device__ __align__(16) __half g_a16[MAXN * 128];  // fp16 aggregation outputs
__device__ __align__(16) __half g_w1t[128 * 128];   // W1^T fp16 [n][k]
__device__ __align__(16) __half g_w2t[128 * 128];   // W2^T fp16 [n][k]
__device__ __align__(16) __half g_w3t[64 * 128];    // W3^T fp16 padded [n][k]
__device__ __align__(16) float  g_dinv[MAXN];
__device__ int   g_cnt[MAXN];     // zero at entry (zero-init + re-zeroed by scan_pass3)
__device__ int   g_rowptr[MAXN + 1];
__device__ int   g_cursor[MAXN];
__device__ int   g_srcidx[MAXE];
__device__ int   g_bsum[MAXB];
__device__ int   g_boff[MAXB];

// ---------------- graph preprocessing ---------------------------------------
__global__ void hist_kernel(const int* __restrict__ ei, int ne) {
    int e = blockIdx.x * blockDim.x + threadIdx.x;
    if (e < ne) {
        int d = ei[ne + e];
        atomicAdd(&g_cnt[d], 1);
    }
}

__global__ void dinv_kernel(int n) {
    int i = blockIdx.x * blockDim.x + threadIdx.x;
    if (i < n) g_dinv[i] = rsqrtf((float)(g_cnt[i] + 1));
}

__global__ void scan_pass1(int n) {
    __shared__ int sh[SCAN_TILE];
    int t = threadIdx.x;
    int i = blockIdx.x * SCAN_TILE + t;
    int v = (i < n) ? g_cnt[i] : 0;
    sh[t] = v;
    __syncthreads();
    for (int off = SCAN_TILE / 2; off > 0; off >>= 1) {
        if (t < off) sh[t] += sh[t + off];
        __syncthreads();
    }
    if (t == 0) g_bsum[blockIdx.x] = sh[0];
}

__global__ void scan_pass2(int nb, int n) {
    __shared__ int sh[SCAN_TILE];
    int t = threadIdx.x;
    int v = (t < nb) ? g_bsum[t] : 0;
    sh[t] = v;
    __syncthreads();
    for (int off = 1; off < SCAN_TILE; off <<= 1) {
        int u = (t >= off) ? sh[t - off] : 0;
        __syncthreads();
        sh[t] += u;
        __syncthreads();
    }
    if (t < nb) g_boff[t] = sh[t] - v;
    if (t == nb - 1) g_rowptr[n] = sh[t];
}

// pass 3 also re-zeroes g_cnt so the next kernel_launch (graph replay) starts clean
__global__ void scan_pass3(int n) {
    __shared__ int sh[SCAN_TILE];
    int t = threadIdx.x;
    int i = blockIdx.x * SCAN_TILE + t;
    int v = (i < n) ? g_cnt[i] : 0;
    sh[t] = v;
    __syncthreads();
    for (int off = 1; off < SCAN_TILE; off <<= 1) {
        int u = (t >= off) ? sh[t - off] : 0;
        __syncthreads();
        sh[t] += u;
        __syncthreads();
    }
    if (i < n) {
        int excl = g_boff[blockIdx.x] + sh[t] - v;
        g_rowptr[i] = excl;
        g_cursor[i] = excl;
        g_cnt[i] = 0;
    }
}

__global__ void fill_kernel(const int* __restrict__ ei, int ne) {
    int e = blockIdx.x * blockDim.x + threadIdx.x;
    if (e < ne) {
        int s = ei[e];
        int d = ei[ne + e];
        int pos = atomicAdd(&g_cursor[d], 1);
        g_srcidx[pos] = s;
    }
}

// W[128 x 128] fp32 -> transposed fp16 [n][k]; destination symbol chosen in
// device code (GB300/ATS pitfall: never pass a __device__ symbol host-side).
template <int WSEL>
__global__ void w128t_kernel(const float* __restrict__ W) {
    __half* out = (WSEL == 1) ? g_w1t : g_w2t;
    int i = blockIdx.x * blockDim.x + threadIdx.x;  // 16384
    int nn = i >> 7, k = i & 127;
    out[i] = __float2half(W[k * 128 + nn]);
}

__global__ void w3t_kernel(const float* __restrict__ W3) {
    int i = blockIdx.x * blockDim.x + threadIdx.x;  // 8192
    int nn = i >> 7, k = i & 127;
    g_w3t[i] = (nn < 40) ? __float2half(W3[k * 40 + nn]) : __half(0.f);
}

// ---------------- HMMA GEMM: h' = (A @ B) * dinv[row], fp16 out -------------
// ASEL: 0 = A is external fp32 x (converted during staging), 1 = g_a16 fp16.
__device__ __forceinline__ void mma16816(float* c, const unsigned* a, const unsigned* b) {
    asm volatile(
        "mma.sync.aligned.m16n8k16.row.col.f32.f16.f16.f32 "
        "{%0,%1,%2,%3}, {%4,%5,%6,%7}, {%8,%9}, {%0,%1,%2,%3};"
        : "+f"(c[0]), "+f"(c[1]), "+f"(c[2]), "+f"(c[3])
        : "r"(a[0]), "r"(a[1]), "r"(a[2]), "r"(a[3]), "r"(b[0]), "r"(b[1]));
}

template <int BN, int ASEL, int WSEL>
__global__ void gemm_hmma(const float* __restrict__ Axf, int M, int ldc) {
    constexpr int LDA = 136;
    constexpr int WARPS_N = BN / 32;
    constexpr int WARPS_M = 8 / WARPS_N;
    constexpr int MT = (128 / WARPS_M) / 16;

    extern __shared__ __half smem[];
    __half* As = smem;                  // [128][LDA]
    __half* Bs = smem + 128 * LDA;      // [BN][LDA]

    const __half* __restrict__ Bt =
        (WSEL == 1) ? (const __half*)g_w1t :
        (WSEL == 2) ? (const __half*)g_w2t : (const __half*)g_w3t;

    int tid = threadIdx.x;
    int rowBase = blockIdx.x * 128;

    if (ASEL == 0) {
        // stage fp32 x tile with inline fp16 conversion (4096 float4 / 256 thr)
#pragma unroll
        for (int l = 0; l < 16; l++) {
            int idx = tid + l * 256;
            int r = idx >> 5;
            int c4 = idx & 31;
            float4 v = make_float4(0.f, 0.f, 0.f, 0.f);
            int grow = rowBase + r;
            if (grow < M) v = *(const float4*)&Axf[grow * 128 + c4 * 4];
            __half2 h[2];
            h[0] = __floats2half2_rn(v.x, v.y);
            h[1] = __floats2half2_rn(v.z, v.w);
            *(uint2*)&As[r * LDA + c4 * 4] = *(uint2*)h;
        }
    } else {
#pragma unroll
        for (int l = 0; l < 8; l++) {
            int idx = tid + l * 256;
            int r = idx >> 4;
            int c = (idx & 15) * 8;
            uint4 v = make_uint4(0, 0, 0, 0);
            int grow = rowBase + r;
            if (grow < M) v = *(const uint4*)&g_a16[grow * 128 + c];
            *(uint4*)&As[r * LDA + c] = v;
        }
    }
#pragma unroll
    for (int l = 0; l < BN / 16; l++) {
        int idx = tid + l * 256;
        int r = idx >> 4;
        int c = (idx & 15) * 8;
        *(uint4*)&Bs[r * LDA + c] = *(const uint4*)&Bt[r * 128 + c];
    }
    __syncthreads();

    int wid = tid >> 5, lane = tid & 31;
    int g = lane >> 2, t = lane & 3;
    int wm = (wid / WARPS_N) * (MT * 16);
    int wn = (wid % WARPS_N) * 32;

    float acc[MT][4][4];
#pragma unroll
    for (int mi = 0; mi < MT; mi++)
#pragma unroll
        for (int ni = 0; ni < 4; ni++)
#pragma unroll
            for (int q = 0; q < 4; q++) acc[mi][ni][q] = 0.f;

#pragma unroll
    for (int ks = 0; ks < 8; ks++) {
        int k0 = ks * 16;
        unsigned afr[MT][4], bfr[4][2];
#pragma unroll
        for (int mi = 0; mi < MT; mi++) {
            const __half* base = &As[(wm + mi * 16 + g) * LDA + k0 + 2 * t];
            afr[mi][0] = *(const unsigned*)(base);
            afr[mi][1] = *(const unsigned*)(base + 8 * LDA);
            afr[mi][2] = *(const unsigned*)(base + 8);
            afr[mi][3] = *(const unsigned*)(base + 8 * LDA + 8);
        }
#pragma unroll
        for (int ni = 0; ni < 4; ni++) {
            const __half* bb = &Bs[(wn + ni * 8 + g) * LDA + k0 + 2 * t];
            bfr[ni][0] = *(const unsigned*)(bb);
            bfr[ni][1] = *(const unsigned*)(bb + 8);
        }
#pragma unroll
        for (int mi = 0; mi < MT; mi++)
#pragma unroll
            for (int ni = 0; ni < 4; ni++)
                mma16816(acc[mi][ni], afr[mi], bfr[ni]);
    }

    // epilogue: scale each row by dinv[row], store fp16
#pragma unroll
    for (int mi = 0; mi < MT; mi++) {
        int r0 = rowBase + wm + mi * 16 + g;
        float s0 = (r0 < M) ? g_dinv[r0] : 0.f;
        float s1 = (r0 + 8 < M) ? g_dinv[r0 + 8] : 0.f;
#pragma unroll
        for (int ni = 0; ni < 4; ni++) {
            int c = wn + ni * 8 + 2 * t;
            if (r0 < M) {
                __half2 h = __floats2half2_rn(acc[mi][ni][0] * s0, acc[mi][ni][1] * s0);
                *(__half2*)&g_h16[r0 * ldc + c] = h;
            }
            if (r0 + 8 < M) {
                __half2 h = __floats2half2_rn(acc[mi][ni][2] * s1, acc[mi][ni][3] * s1);
                *(__half2*)&g_h16[(r0 + 8) * ldc + c] = h;
            }
        }
    }
}

// ---------------- aggregation (F=128), warp/node, pure row sum --------------
__device__ __forceinline__ void cvt8(uint4 r, float* f) {
    __half2* p = (__half2*)&r;
    float2 a = __half22float2(p[0]);
    float2 b = __half22float2(p[1]);
    float2 c = __half22float2(p[2]);
    float2 d = __half22float2(p[3]);
    f[0] = a.x; f[1] = a.y; f[2] = b.x; f[3] = b.y;
    f[4] = c.x; f[5] = c.y; f[6] = d.x; f[7] = d.y;
}

__global__ void agg128_kernel(const float* __restrict__ bias, int n, int do_relu) {
    int gw = (blockIdx.x * blockDim.x + threadIdx.x) >> 5;
    if (gw >= n) return;
    int lane = threadIdx.x & 31;
    int hf = lane >> 4;        // which edge of each pair
    int sub = lane & 15;       // 16B chunk within the 256B row
    const uint4* __restrict__ hv = (const uint4*)g_h16;

    float acc[8];
    {   // self-loop h'[d]: each half adds 0.5x (exact after combine)
        float f[8];
        cvt8(hv[gw * 16 + sub], f);
#pragma unroll
        for (int q = 0; q < 8; q++) acc[q] = 0.5f * f[q];
    }

    int beg = g_rowptr[gw];
    int end = g_rowptr[gw + 1];
    int i = beg;
    // 8 edges per iteration: 4 independent uint4 loads in flight per lane
    for (; i + 7 < end; i += 8) {
        int sa = g_srcidx[i + 0 + hf];
        int sb = g_srcidx[i + 2 + hf];
        int sc = g_srcidx[i + 4 + hf];
        int sd = g_srcidx[i + 6 + hf];
        uint4 ra = hv[sa * 16 + sub];
        uint4 rb = hv[sb * 16 + sub];
        uint4 rc = hv[sc * 16 + sub];
        uint4 rd = hv[sd * 16 + sub];
        float fa[8], fb[8], fc[8], fd[8];
        cvt8(ra, fa);
        cvt8(rb, fb);
        cvt8(rc, fc);
        cvt8(rd, fd);
#pragma unroll
        for (int q = 0; q < 8; q++) acc[q] += (fa[q] + fb[q]) + (fc[q] + fd[q]);
    }
    for (; i + 1 < end; i += 2) {
        int sa = g_srcidx[i + hf];
        uint4 ra = hv[sa * 16 + sub];
        float fa[8];
        cvt8(ra, fa);
#pragma unroll
        for (int q = 0; q < 8; q++) acc[q] += fa[q];
    }
    if (i < end) {  // odd remainder: half 1 contributes 0
        int s0 = g_srcidx[i];
        float w = hf ? 0.f : 1.f;
        uint4 ra = hv[s0 * 16 + sub];
        float fa[8];
        cvt8(ra, fa);
#pragma unroll
        for (int q = 0; q < 8; q++) acc[q] += w * fa[q];
    }
#pragma unroll
    for (int q = 0; q < 8; q++) acc[q] += __shfl_xor_sync(0xFFFFFFFFu, acc[q], 16);

    float dd = g_dinv[gw];
    float4 b0 = ((const float4*)bias)[sub * 2];
    float4 b1 = ((const float4*)bias)[sub * 2 + 1];
    acc[0] = acc[0] * dd + b0.x; acc[1] = acc[1] * dd + b0.y;
    acc[2] = acc[2] * dd + b0.z; acc[3] = acc[3] * dd + b0.w;
    acc[4] = acc[4] * dd + b1.x; acc[5] = acc[5] * dd + b1.y;
    acc[6] = acc[6] * dd + b1.z; acc[7] = acc[7] * dd + b1.w;
    if (do_relu) {
#pragma unroll
        for (int q = 0; q < 8; q++) acc[q] = fmaxf(acc[q], 0.f);
    }
    if (hf == 0) {
        __half2 o[4];
        o[0] = __floats2half2_rn(acc[0], acc[1]);
        o[1] = __floats2half2_rn(acc[2], acc[3]);
        o[2] = __floats2half2_rn(acc[4], acc[5]);
        o[3] = __floats2half2_rn(acc[6], acc[7]);
        *(uint4*)&g_a16[gw * 128 + sub * 8] = *(uint4*)o;
    }
}

// ---------------- layer 3 aggregation (F=40, fp16 h' stride 64) + softmax ---
__global__ void agg40_softmax_kernel(const float* __restrict__ b3,
                                     float* __restrict__ out, int n) {
    int gw = (blockIdx.x * blockDim.x + threadIdx.x) >> 5;
    if (gw >= n) return;
    int lane = threadIdx.x & 31;
    bool act = lane < 20;
    const __half2* __restrict__ hv = (const __half2*)g_h16;  // row stride = 32 half2

    float2 acc = make_float2(0.f, 0.f);
    if (act) {
        float2 v = __half22float2(hv[gw * 32 + lane]);  // self h'[d]
        acc.x = v.x;
        acc.y = v.y;
    }
    int beg = g_rowptr[gw];
    int end = g_rowptr[gw + 1];
    int i = beg;
    for (; i + 1 < end; i += 2) {
        int s0 = g_srcidx[i], s1 = g_srcidx[i + 1];
        if (act) {
            float2 v0 = __half22float2(hv[s0 * 32 + lane]);
            float2 v1 = __half22float2(hv[s1 * 32 + lane]);
            acc.x += v0.x + v1.x;
            acc.y += v0.y + v1.y;
        }
    }
    if (i < end) {
        int s = g_srcidx[i];
        if (act) {
            float2 v = __half22float2(hv[s * 32 + lane]);
            acc.x += v.x;
            acc.y += v.y;
        }
    }
    if (act) {
        float dd = g_dinv[gw];
        acc.x = acc.x * dd + b3[lane * 2];
        acc.y = acc.y * dd + b3[lane * 2 + 1];
    }
    float m = act ? fmaxf(acc.x, acc.y) : -INFINITY;
#pragma unroll
    for (int off = 16; off > 0; off >>= 1) m = fmaxf(m, __shfl_xor_sync(0xFFFFFFFFu, m, off));
    float se = act ? (expf(acc.x - m) + expf(acc.y - m)) : 0.f;
#pragma unroll
    for (int off = 16; off > 0; off >>= 1) se += __shfl_xor_sync(0xFFFFFFFFu, se, off);
    float ls = m + logf(se);
    if (act) {
        out[gw * 40 + lane * 2 + 0] = acc.x - ls;
        out[gw * 40 + lane * 2 + 1] = acc.y - ls;
    }
}

// ---------------- launch -----------------------------------------------------
extern "C" void kernel_launch(void* const* d_in, const int* in_sizes, int n_in,
                              void* d_out, int out_size) {
    const float* x = (const float*)d_in[0];
    const int* ei = (const int*)d_in[1];
    const float* W1 = (const float*)d_in[2];
    const float* b1 = (const float*)d_in[3];
    const float* W2 = (const float*)d_in[4];
    const float* b2 = (const float*)d_in[5];
    const float* W3 = (const float*)d_in[6];
    const float* b3 = (const float*)d_in[7];
    float* out = (float*)d_out;

    const int n = in_sizes[0] / 128;   // 50000
    const int ne = in_sizes[1] / 2;    // 1600000

    int nb = (n + 255) / 256;
    int eb = (ne + 255) / 256;
    int wb = (n + 7) / 8;
    int sb = (n + SCAN_TILE - 1) / SCAN_TILE;
    int gb = (n + 127) / 128;

    const int SMEM_128 = (128 + 128) * 136 * 2;  // 69632
    const int SMEM_64  = (128 + 64) * 136 * 2;   // 52224
    cudaFuncSetAttribute((const void*)gemm_hmma<128, 0, 1>,
                         cudaFuncAttributeMaxDynamicSharedMemorySize, SMEM_128);
    cudaFuncSetAttribute((const void*)gemm_hmma<128, 1, 2>,
                         cudaFuncAttributeMaxDynamicSharedMemorySize, SMEM_128);
    cudaFuncSetAttribute((const void*)gemm_hmma<64, 1, 3>,
                         cudaFuncAttributeMaxDynamicSharedMemorySize, SMEM_64);

    // g_cnt is zero at entry (zero-init on load; scan_pass3 re-zeroes each run)
    hist_kernel<<<eb, 256>>>(ei, ne);
    dinv_kernel<<<nb, 256>>>(n);
    w128t_kernel<1><<<64, 256>>>(W1);
    gemm_hmma<128, 0, 1><<<gb, 256, SMEM_128>>>(x, n, 128);  // profiled slot 4
    scan_pass1<<<sb, SCAN_TILE>>>(n);
    scan_pass2<<<1, SCAN_TILE>>>(sb, n);
    scan_pass3<<<sb, SCAN_TILE>>>(n);
    fill_kernel<<<eb, 256>>>(ei, ne);
    w128t_kernel<2><<<64, 256>>>(W2);
    w3t_kernel<<<32, 256>>>(W3);

    // layer 1 aggregation
    agg128_kernel<<<wb, 256>>>(b1, n, 1);
    // layer 2
    gemm_hmma<128, 1, 2><<<gb, 256, SMEM_128>>>(nullptr, n, 128);
    agg128_kernel<<<wb, 256>>>(b2, n, 1);
    // layer 3
    gemm_hmma<64, 1, 3><<<gb, 256, SMEM_64>>>(nullptr, n, 64);
    agg40_softmax_kernel<<<wb, 256>>>(b3, out, n);
}

// round 14
// speedup vs baseline: 2.4319x; 1.0114x over previous
#include <cuda_runtime.h>
#include <cuda_bf16.h>
#include <cuda_fp16.h>
#include <math.h>

#define MAXN 50000
#define MAXE 1600000
#define SCAN_TILE 256
#define MAXB ((MAXN + SCAN_TILE - 1) / SCAN_TILE)

// ---------------- scratch ----------------------------------------------------
__device__ __align__(16) __half g_h16[MAXN * 128];  // fp16 GEMM out, pre-scaled by dinv[row]
__device__ __align__(16) __half g_a16[MAXN * 128];  // fp16 aggregation outputs
__device__ __align__(16) __half g_w1t[128 * 128];   // W1^T fp16 [n][k]
__device__ __align__(16) __half g_w2t[128 * 128];   // W2^T fp16 [n][k]
__device__ __align__(16) __half g_w3t[64 * 128];    // W3^T fp16 padded [n][k]
__device__ __align__(16) float  g_dinv[MAXN];
__device__ int   g_cnt[MAXN];     // zero at entry (zero-init + re-zeroed by scan_pass3)
__device__ int   g_rowptr[MAXN + 1];
__device__ int   g_cursor[MAXN];
__device__ int   g_srcidx[MAXE];
__device__ int   g_bsum[MAXB];
__device__ int   g_boff[MAXB];

// ---------------- graph preprocessing ---------------------------------------
__global__ void hist_kernel(const int* __restrict__ ei, int ne) {
    int e = blockIdx.x * blockDim.x + threadIdx.x;
    if (e < ne) {
        int d = ei[ne + e];
        atomicAdd(&g_cnt[d], 1);
    }
}

__global__ void dinv_kernel(int n) {
    int i = blockIdx.x * blockDim.x + threadIdx.x;
    if (i < n) g_dinv[i] = rsqrtf((float)(g_cnt[i] + 1));
}

__global__ void scan_pass1(int n) {
    __shared__ int sh[SCAN_TILE];
    int t = threadIdx.x;
    int i = blockIdx.x * SCAN_TILE + t;
    int v = (i < n) ? g_cnt[i] : 0;
    sh[t] = v;
    __syncthreads();
    for (int off = SCAN_TILE / 2; off > 0; off >>= 1) {
        if (t < off) sh[t] += sh[t + off];
        __syncthreads();
    }
    if (t == 0) g_bsum[blockIdx.x] = sh[0];
}

__global__ void scan_pass2(int nb, int n) {
    __shared__ int sh[SCAN_TILE];
    int t = threadIdx.x;
    int v = (t < nb) ? g_bsum[t] : 0;
    sh[t] = v;
    __syncthreads();
    for (int off = 1; off < SCAN_TILE; off <<= 1) {
        int u = (t >= off) ? sh[t - off] : 0;
        __syncthreads();
        sh[t] += u;
        __syncthreads();
    }
    if (t < nb) g_boff[t] = sh[t] - v;
    if (t == nb - 1) g_rowptr[n] = sh[t];
}

// pass 3 also re-zeroes g_cnt so the next launch/graph replay starts clean
__global__ void scan_pass3(int n) {
    __shared__ int sh[SCAN_TILE];
    int t = threadIdx.x;
    int i = blockIdx.x * SCAN_TILE + t;
    int v = (i < n) ? g_cnt[i] : 0;
    sh[t] = v;
    __syncthreads();
    for (int off = 1; off < SCAN_TILE; off <<= 1) {
        int u = (t >= off) ? sh[t - off] : 0;
        __syncthreads();
        sh[t] += u;
        __syncthreads();
    }
    if (i < n) {
        int excl = g_boff[blockIdx.x] + sh[t] - v;
        g_rowptr[i] = excl;
        g_cursor[i] = excl;
        g_cnt[i] = 0;
    }
}

__global__ void fill_kernel(const int* __restrict__ ei, int ne) {
    int e = blockIdx.x * blockDim.x + threadIdx.x;
    if (e < ne) {
        int s = ei[e];
        int d = ei[ne + e];
        int pos = atomicAdd(&g_cursor[d], 1);
        g_srcidx[pos] = s;
    }
}

// W[128 x 128] fp32 -> transposed fp16 [n][k]; destination symbol chosen in
// device code (GB300/ATS pitfall: never pass a __device__ symbol host-side).
template <int WSEL>
__global__ void w128t_kernel(const float* __restrict__ W) {
    __half* out = (WSEL == 1) ? g_w1t : g_w2t;
    int i = blockIdx.x * blockDim.x + threadIdx.x;  // 16384
    int nn = i >> 7, k = i & 127;
    out[i] = __float2half(W[k * 128 + nn]);
}

__global__ void w3t_kernel(const float* __restrict__ W3) {
    int i = blockIdx.x * blockDim.x + threadIdx.x;  // 8192
    int nn = i >> 7, k = i & 127;
    g_w3t[i] = (nn < 40) ? __float2half(W3[k * 40 + nn]) : __half(0.f);
}

// ---------------- HMMA GEMM: h' = (A @ B) * dinv[row], fp16 out -------------
// BM=64 tile, 8 warps, >=3 CTAs/SM for occupancy.
// ASEL: 0 = A is external fp32 x (converted during staging), 1 = g_a16 fp16.
__device__ __forceinline__ void mma16816(float* c, const unsigned* a, const unsigned* b) {
    asm volatile(
        "mma.sync.aligned.m16n8k16.row.col.f32.f16.f16.f32 "
        "{%0,%1,%2,%3}, {%4,%5,%6,%7}, {%8,%9}, {%0,%1,%2,%3};"
        : "+f"(c[0]), "+f"(c[1]), "+f"(c[2]), "+f"(c[3])
        : "r"(a[0]), "r"(a[1]), "r"(a[2]), "r"(a[3]), "r"(b[0]), "r"(b[1]));
}

template <int BN, int ASEL, int WSEL>
__global__ void __launch_bounds__(256, 3)
gemm_hmma(const float* __restrict__ Axf, int M, int ldc) {
    constexpr int LDA = 136;
    constexpr int WARPS_N = BN / 32;           // 4 (BN=128) or 2 (BN=64)
    constexpr int WARPS_M = 8 / WARPS_N;       // 2 or 4
    constexpr int MT = (64 / WARPS_M) / 16;    // 2 or 1

    extern __shared__ __half smem[];
    __half* As = smem;                  // [64][LDA]
    __half* Bs = smem + 64 * LDA;       // [BN][LDA]

    const __half* __restrict__ Bt =
        (WSEL == 1) ? (const __half*)g_w1t :
        (WSEL == 2) ? (const __half*)g_w2t : (const __half*)g_w3t;

    int tid = threadIdx.x;
    int rowBase = blockIdx.x * 64;

    if (ASEL == 0) {
        // stage fp32 x tile (64 x 32 float4) with inline fp16 conversion
#pragma unroll
        for (int l = 0; l < 8; l++) {
            int idx = tid + l * 256;
            int r = idx >> 5;
            int c4 = idx & 31;
            float4 v = make_float4(0.f, 0.f, 0.f, 0.f);
            int grow = rowBase + r;
            if (grow < M) v = *(const float4*)&Axf[grow * 128 + c4 * 4];
            __half2 h[2];
            h[0] = __floats2half2_rn(v.x, v.y);
            h[1] = __floats2half2_rn(v.z, v.w);
            *(uint2*)&As[r * LDA + c4 * 4] = *(uint2*)h;
        }
    } else {
        // stage fp16 a tile (64 x 16 uint4)
#pragma unroll
        for (int l = 0; l < 4; l++) {
            int idx = tid + l * 256;
            int r = idx >> 4;
            int c = (idx & 15) * 8;
            uint4 v = make_uint4(0, 0, 0, 0);
            int grow = rowBase + r;
            if (grow < M) v = *(const uint4*)&g_a16[grow * 128 + c];
            *(uint4*)&As[r * LDA + c] = v;
        }
    }
#pragma unroll
    for (int l = 0; l < BN / 16; l++) {
        int idx = tid + l * 256;
        int r = idx >> 4;
        int c = (idx & 15) * 8;
        *(uint4*)&Bs[r * LDA + c] = *(const uint4*)&Bt[r * 128 + c];
    }
    __syncthreads();

    int wid = tid >> 5, lane = tid & 31;
    int g = lane >> 2, t = lane & 3;
    int wm = (wid / WARPS_N) * (MT * 16);
    int wn = (wid % WARPS_N) * 32;

    float acc[MT][4][4];
#pragma unroll
    for (int mi = 0; mi < MT; mi++)
#pragma unroll
        for (int ni = 0; ni < 4; ni++)
#pragma unroll
            for (int q = 0; q < 4; q++) acc[mi][ni][q] = 0.f;

#pragma unroll
    for (int ks = 0; ks < 8; ks++) {
        int k0 = ks * 16;
        unsigned afr[MT][4], bfr[4][2];
#pragma unroll
        for (int mi = 0; mi < MT; mi++) {
            const __half* base = &As[(wm + mi * 16 + g) * LDA + k0 + 2 * t];
            afr[mi][0] = *(const unsigned*)(base);
            afr[mi][1] = *(const unsigned*)(base + 8 * LDA);
            afr[mi][2] = *(const unsigned*)(base + 8);
            afr[mi][3] = *(const unsigned*)(base + 8 * LDA + 8);
        }
#pragma unroll
        for (int ni = 0; ni < 4; ni++) {
            const __half* bb = &Bs[(wn + ni * 8 + g) * LDA + k0 + 2 * t];
            bfr[ni][0] = *(const unsigned*)(bb);
            bfr[ni][1] = *(const unsigned*)(bb + 8);
        }
#pragma unroll
        for (int mi = 0; mi < MT; mi++)
#pragma unroll
            for (int ni = 0; ni < 4; ni++)
                mma16816(acc[mi][ni], afr[mi], bfr[ni]);
    }

    // epilogue: scale each row by dinv[row], store fp16
#pragma unroll
    for (int mi = 0; mi < MT; mi++) {
        int r0 = rowBase + wm + mi * 16 + g;
        float s0 = (r0 < M) ? g_dinv[r0] : 0.f;
        float s1 = (r0 + 8 < M) ? g_dinv[r0 + 8] : 0.f;
#pragma unroll
        for (int ni = 0; ni < 4; ni++) {
            int c = wn + ni * 8 + 2 * t;
            if (r0 < M) {
                __half2 h = __floats2half2_rn(acc[mi][ni][0] * s0, acc[mi][ni][1] * s0);
                *(__half2*)&g_h16[r0 * ldc + c] = h;
            }
            if (r0 + 8 < M) {
                __half2 h = __floats2half2_rn(acc[mi][ni][2] * s1, acc[mi][ni][3] * s1);
                *(__half2*)&g_h16[(r0 + 8) * ldc + c] = h;
            }
        }
    }
}

// ---------------- aggregation (F=128), warp/node, pure row sum --------------
__device__ __forceinline__ void cvt8(uint4 r, float* f) {
    __half2* p = (__half2*)&r;
    float2 a = __half22float2(p[0]);
    float2 b = __half22float2(p[1]);
    float2 c = __half22float2(p[2]);
    float2 d = __half22float2(p[3]);
    f[0] = a.x; f[1] = a.y; f[2] = b.x; f[3] = b.y;
    f[4] = c.x; f[5] = c.y; f[6] = d.x; f[7] = d.y;
}

__global__ void agg128_kernel(const float* __restrict__ bias, int n, int do_relu) {
    int gw = (blockIdx.x * blockDim.x + threadIdx.x) >> 5;
    if (gw >= n) return;
    int lane = threadIdx.x & 31;
    int hf = lane >> 4;        // which edge of each pair
    int sub = lane & 15;       // 16B chunk within the 256B row
    const uint4* __restrict__ hv = (const uint4*)g_h16;

    float acc[8];
    {   // self-loop h'[d]: each half adds 0.5x (exact after combine)
        float f[8];
        cvt8(hv[gw * 16 + sub], f);
#pragma unroll
        for (int q = 0; q < 8; q++) acc[q] = 0.5f * f[q];
    }

    int beg = g_rowptr[gw];
    int end = g_rowptr[gw + 1];
    int i = beg;
    for (; i + 7 < end; i += 8) {
        int sa = g_srcidx[i + 0 + hf];
        int sb = g_srcidx[i + 2 + hf];
        int sc = g_srcidx[i + 4 + hf];
        int sd = g_srcidx[i + 6 + hf];
        uint4 ra = hv[sa * 16 + sub];
        uint4 rb = hv[sb * 16 + sub];
        uint4 rc = hv[sc * 16 + sub];
        uint4 rd = hv[sd * 16 + sub];
        float fa[8], fb[8], fc[8], fd[8];
        cvt8(ra, fa);
        cvt8(rb, fb);
        cvt8(rc, fc);
        cvt8(rd, fd);
#pragma unroll
        for (int q = 0; q < 8; q++) acc[q] += (fa[q] + fb[q]) + (fc[q] + fd[q]);
    }
    for (; i + 1 < end; i += 2) {
        int sa = g_srcidx[i + hf];
        uint4 ra = hv[sa * 16 + sub];
        float fa[8];
        cvt8(ra, fa);
#pragma unroll
        for (int q = 0; q < 8; q++) acc[q] += fa[q];
    }
    if (i < end) {
        int s0 = g_srcidx[i];
        float w = hf ? 0.f : 1.f;
        uint4 ra = hv[s0 * 16 + sub];
        float fa[8];
        cvt8(ra, fa);
#pragma unroll
        for (int q = 0; q < 8; q++) acc[q] += w * fa[q];
    }
#pragma unroll
    for (int q = 0; q < 8; q++) acc[q] += __shfl_xor_sync(0xFFFFFFFFu, acc[q], 16);

    float dd = g_dinv[gw];
    float4 b0 = ((const float4*)bias)[sub * 2];
    float4 b1 = ((const float4*)bias)[sub * 2 + 1];
    acc[0] = acc[0] * dd + b0.x; acc[1] = acc[1] * dd + b0.y;
    acc[2] = acc[2] * dd + b0.z; acc[3] = acc[3] * dd + b0.w;
    acc[4] = acc[4] * dd + b1.x; acc[5] = acc[5] * dd + b1.y;
    acc[6] = acc[6] * dd + b1.z; acc[7] = acc[7] * dd + b1.w;
    if (do_relu) {
#pragma unroll
        for (int q = 0; q < 8; q++) acc[q] = fmaxf(acc[q], 0.f);
    }
    if (hf == 0) {
        __half2 o[4];
        o[0] = __floats2half2_rn(acc[0], acc[1]);
        o[1] = __floats2half2_rn(acc[2], acc[3]);
        o[2] = __floats2half2_rn(acc[4], acc[5]);
        o[3] = __floats2half2_rn(acc[6], acc[7]);
        *(uint4*)&g_a16[gw * 128 + sub * 8] = *(uint4*)o;
    }
}

// ---------------- layer 3 aggregation (F=40, fp16 h' stride 64) + softmax ---
__global__ void agg40_softmax_kernel(const float* __restrict__ b3,
                                     float* __restrict__ out, int n) {
    int gw = (blockIdx.x * blockDim.x + threadIdx.x) >> 5;
    if (gw >= n) return;
    int lane = threadIdx.x & 31;
    bool act = lane < 20;
    const __half2* __restrict__ hv = (const __half2*)g_h16;  // row stride = 32 half2

    float2 acc = make_float2(0.f, 0.f);
    if (act) {
        float2 v = __half22float2(hv[gw * 32 + lane]);  // self h'[d]
        acc.x = v.x;
        acc.y = v.y;
    }
    int beg = g_rowptr[gw];
    int end = g_rowptr[gw + 1];
    int i = beg;
    for (; i + 1 < end; i += 2) {
        int s0 = g_srcidx[i], s1 = g_srcidx[i + 1];
        if (act) {
            float2 v0 = __half22float2(hv[s0 * 32 + lane]);
            float2 v1 = __half22float2(hv[s1 * 32 + lane]);
            acc.x += v0.x + v1.x;
            acc.y += v0.y + v1.y;
        }
    }
    if (i < end) {
        int s = g_srcidx[i];
        if (act) {
            float2 v = __half22float2(hv[s * 32 + lane]);
            acc.x += v.x;
            acc.y += v.y;
        }
    }
    if (act) {
        float dd = g_dinv[gw];
        acc.x = acc.x * dd + b3[lane * 2];
        acc.y = acc.y * dd + b3[lane * 2 + 1];
    }
    float m = act ? fmaxf(acc.x, acc.y) : -INFINITY;
#pragma unroll
    for (int off = 16; off > 0; off >>= 1) m = fmaxf(m, __shfl_xor_sync(0xFFFFFFFFu, m, off));
    float se = act ? (expf(acc.x - m) + expf(acc.y - m)) : 0.f;
#pragma unroll
    for (int off = 16; off > 0; off >>= 1) se += __shfl_xor_sync(0xFFFFFFFFu, se, off);
    float ls = m + logf(se);
    if (act) {
        out[gw * 40 + lane * 2 + 0] = acc.x - ls;
        out[gw * 40 + lane * 2 + 1] = acc.y - ls;
    }
}

// ---------------- launch -----------------------------------------------------
extern "C" void kernel_launch(void* const* d_in, const int* in_sizes, int n_in,
                              void* d_out, int out_size) {
    const float* x = (const float*)d_in[0];
    const int* ei = (const int*)d_in[1];
    const float* W1 = (const float*)d_in[2];
    const float* b1 = (const float*)d_in[3];
    const float* W2 = (const float*)d_in[4];
    const float* b2 = (const float*)d_in[5];
    const float* W3 = (const float*)d_in[6];
    const float* b3 = (const float*)d_in[7];
    float* out = (float*)d_out;

    const int n = in_sizes[0] / 128;   // 50000
    const int ne = in_sizes[1] / 2;    // 1600000

    int nb = (n + 255) / 256;
    int eb = (ne + 255) / 256;
    int wb = (n + 7) / 8;
    int sb = (n + SCAN_TILE - 1) / SCAN_TILE;
    int gb = (n + 63) / 64;

    const int SMEM_128 = (64 + 128) * 136 * 2;  // 52224
    const int SMEM_64  = (64 + 64) * 136 * 2;   // 34816
    cudaFuncSetAttribute((const void*)gemm_hmma<128, 0, 1>,
                         cudaFuncAttributeMaxDynamicSharedMemorySize, SMEM_128);
    cudaFuncSetAttribute((const void*)gemm_hmma<128, 1, 2>,
                         cudaFuncAttributeMaxDynamicSharedMemorySize, SMEM_128);
    cudaFuncSetAttribute((const void*)gemm_hmma<64, 1, 3>,
                         cudaFuncAttributeMaxDynamicSharedMemorySize, SMEM_64);

    // g_cnt is zero at entry (zero-init on load; scan_pass3 re-zeroes each run)
    hist_kernel<<<eb, 256>>>(ei, ne);
    dinv_kernel<<<nb, 256>>>(n);
    w128t_kernel<1><<<64, 256>>>(W1);
    gemm_hmma<128, 0, 1><<<gb, 256, SMEM_128>>>(x, n, 128);  // profiled slot 4
    scan_pass1<<<sb, SCAN_TILE>>>(n);
    scan_pass2<<<1, SCAN_TILE>>>(sb, n);
    scan_pass3<<<sb, SCAN_TILE>>>(n);
    fill_kernel<<<eb, 256>>>(ei, ne);
    w128t_kernel<2><<<64, 256>>>(W2);
    w3t_kernel<<<32, 256>>>(W3);

    // layer 1 aggregation
    agg128_kernel<<<wb, 256>>>(b1, n, 1);
    // layer 2
    gemm_hmma<128, 1, 2><<<gb, 256, SMEM_128>>>(nullptr, n, 128);
    agg128_kernel<<<wb, 256>>>(b2, n, 1);
    // layer 3
    gemm_hmma<64, 1, 3><<<gb, 256, SMEM_64>>>(nullptr, n, 64);
    agg40_softmax_kernel<<<wb, 256>>>(b3, out, n);
}

// round 15
// speedup vs baseline: 2.4595x; 1.0113x over previous
#include <cuda_runtime.h>
#include <cuda_bf16.h>
#include <cuda_fp16.h>
#include <math.h>

#define MAXN 50000
#define MAXE 1600000
#define SCAN_TILE 256
#define MAXB ((MAXN + SCAN_TILE - 1) / SCAN_TILE)

// ---------------- scratch ----------------------------------------------------
__device__ __align__(16) __half g_h16[MAXN * 128];  // fp16 GEMM out, pre-scaled by dinv[row]
__device__ __align__(16) __half g_a16[MAXN * 128];  // fp16 aggregation outputs
__device__ __align__(16) __half g_w1t[128 * 128];   // W1^T fp16 [n][k]
__device__ __align__(16) __half g_w2t[128 * 128];   // W2^T fp16 [n][k]
__device__ __align__(16) __half g_w3t[64 * 128];    // W3^T fp16 padded [n][k]
__device__ __align__(16) float  g_dinv[MAXN];
__device__ int   g_cnt[MAXN];     // zero at entry (zero-init + re-zeroed by scan_pass3)
__device__ int   g_rowptr[MAXN + 1];
__device__ int   g_cursor[MAXN];
__device__ int   g_srcidx[MAXE];
__device__ int   g_bsum[MAXB];
__device__ int   g_boff[MAXB];

// ---------------- graph preprocessing ---------------------------------------
__global__ void hist_kernel(const int* __restrict__ ei, int ne) {
    int e = blockIdx.x * blockDim.x + threadIdx.x;
    if (e < ne) {
        int d = ei[ne + e];
        atomicAdd(&g_cnt[d], 1);
    }
}

// pass 1 also computes dinv (fused: reads g_cnt anyway)
__global__ void scan_pass1(int n) {
    __shared__ int sh[SCAN_TILE];
    int t = threadIdx.x;
    int i = blockIdx.x * SCAN_TILE + t;
    int v = (i < n) ? g_cnt[i] : 0;
    if (i < n) g_dinv[i] = rsqrtf((float)(v + 1));  // +1 self-loop
    sh[t] = v;
    __syncthreads();
    for (int off = SCAN_TILE / 2; off > 0; off >>= 1) {
        if (t < off) sh[t] += sh[t + off];
        __syncthreads();
    }
    if (t == 0) g_bsum[blockIdx.x] = sh[0];
}

__global__ void scan_pass2(int nb, int n) {
    __shared__ int sh[SCAN_TILE];
    int t = threadIdx.x;
    int v = (t < nb) ? g_bsum[t] : 0;
    sh[t] = v;
    __syncthreads();
    for (int off = 1; off < SCAN_TILE; off <<= 1) {
        int u = (t >= off) ? sh[t - off] : 0;
        __syncthreads();
        sh[t] += u;
        __syncthreads();
    }
    if (t < nb) g_boff[t] = sh[t] - v;
    if (t == nb - 1) g_rowptr[n] = sh[t];
}

// pass 3 also re-zeroes g_cnt so the next launch/graph replay starts clean
__global__ void scan_pass3(int n) {
    __shared__ int sh[SCAN_TILE];
    int t = threadIdx.x;
    int i = blockIdx.x * SCAN_TILE + t;
    int v = (i < n) ? g_cnt[i] : 0;
    sh[t] = v;
    __syncthreads();
    for (int off = 1; off < SCAN_TILE; off <<= 1) {
        int u = (t >= off) ? sh[t - off] : 0;
        __syncthreads();
        sh[t] += u;
        __syncthreads();
    }
    if (i < n) {
        int excl = g_boff[blockIdx.x] + sh[t] - v;
        g_rowptr[i] = excl;
        g_cursor[i] = excl;
        g_cnt[i] = 0;
    }
}

__global__ void fill_kernel(const int* __restrict__ ei, int ne) {
    int e = blockIdx.x * blockDim.x + threadIdx.x;
    if (e < ne) {
        int s = ei[e];
        int d = ei[ne + e];
        int pos = atomicAdd(&g_cursor[d], 1);
        g_srcidx[pos] = s;
    }
}

// All three weight transposes fused; destinations are device symbols referenced
// in device code (GB300/ATS pitfall: never pass a __device__ symbol host-side).
__global__ void wt_all_kernel(const float* __restrict__ W1,
                              const float* __restrict__ W2,
                              const float* __restrict__ W3) {
    int i = blockIdx.x * blockDim.x + threadIdx.x;  // 0..40959
    if (i < 16384) {
        int nn = i >> 7, k = i & 127;
        g_w1t[i] = __float2half(W1[k * 128 + nn]);
    } else if (i < 32768) {
        int j = i - 16384;
        int nn = j >> 7, k = j & 127;
        g_w2t[j] = __float2half(W2[k * 128 + nn]);
    } else if (i < 40960) {
        int j = i - 32768;
        int nn = j >> 7, k = j & 127;
        g_w3t[j] = (nn < 40) ? __float2half(W3[k * 40 + nn]) : __half(0.f);
    }
}

// ---------------- HMMA GEMM: h' = (A @ B) * dinv[row], fp16 out -------------
// BM=64 tile, 8 warps, 4 CTAs/SM (regs capped at 64).
__device__ __forceinline__ void mma16816(float* c, const unsigned* a, const unsigned* b) {
    asm volatile(
        "mma.sync.aligned.m16n8k16.row.col.f32.f16.f16.f32 "
        "{%0,%1,%2,%3}, {%4,%5,%6,%7}, {%8,%9}, {%0,%1,%2,%3};"
        : "+f"(c[0]), "+f"(c[1]), "+f"(c[2]), "+f"(c[3])
        : "r"(a[0]), "r"(a[1]), "r"(a[2]), "r"(a[3]), "r"(b[0]), "r"(b[1]));
}

template <int BN, int ASEL, int WSEL>
__global__ void __launch_bounds__(256, 4)
gemm_hmma(const float* __restrict__ Axf, int M, int ldc) {
    constexpr int LDA = 136;
    constexpr int WARPS_N = BN / 32;           // 4 (BN=128) or 2 (BN=64)
    constexpr int WARPS_M = 8 / WARPS_N;       // 2 or 4
    constexpr int MT = (64 / WARPS_M) / 16;    // 2 or 1

    extern __shared__ __half smem[];
    __half* As = smem;                  // [64][LDA]
    __half* Bs = smem + 64 * LDA;       // [BN][LDA]

    const __half* __restrict__ Bt =
        (WSEL == 1) ? (const __half*)g_w1t :
        (WSEL == 2) ? (const __half*)g_w2t : (const __half*)g_w3t;

    int tid = threadIdx.x;
    int rowBase = blockIdx.x * 64;

    if (ASEL == 0) {
        // stage fp32 x tile (64 x 32 float4) with inline fp16 conversion
#pragma unroll
        for (int l = 0; l < 8; l++) {
            int idx = tid + l * 256;
            int r = idx >> 5;
            int c4 = idx & 31;
            float4 v = make_float4(0.f, 0.f, 0.f, 0.f);
            int grow = rowBase + r;
            if (grow < M) v = *(const float4*)&Axf[grow * 128 + c4 * 4];
            __half2 h[2];
            h[0] = __floats2half2_rn(v.x, v.y);
            h[1] = __floats2half2_rn(v.z, v.w);
            *(uint2*)&As[r * LDA + c4 * 4] = *(uint2*)h;
        }
    } else {
        // stage fp16 a tile (64 x 16 uint4)
#pragma unroll
        for (int l = 0; l < 4; l++) {
            int idx = tid + l * 256;
            int r = idx >> 4;
            int c = (idx & 15) * 8;
            uint4 v = make_uint4(0, 0, 0, 0);
            int grow = rowBase + r;
            if (grow < M) v = *(const uint4*)&g_a16[grow * 128 + c];
            *(uint4*)&As[r * LDA + c] = v;
        }
    }
#pragma unroll
    for (int l = 0; l < BN / 16; l++) {
        int idx = tid + l * 256;
        int r = idx >> 4;
        int c = (idx & 15) * 8;
        *(uint4*)&Bs[r * LDA + c] = *(const uint4*)&Bt[r * 128 + c];
    }
    __syncthreads();

    int wid = tid >> 5, lane = tid & 31;
    int g = lane >> 2, t = lane & 3;
    int wm = (wid / WARPS_N) * (MT * 16);
    int wn = (wid % WARPS_N) * 32;

    float acc[MT][4][4];
#pragma unroll
    for (int mi = 0; mi < MT; mi++)
#pragma unroll
        for (int ni = 0; ni < 4; ni++)
#pragma unroll
            for (int q = 0; q < 4; q++) acc[mi][ni][q] = 0.f;

#pragma unroll
    for (int ks = 0; ks < 8; ks++) {
        int k0 = ks * 16;
        unsigned afr[MT][4], bfr[4][2];
#pragma unroll
        for (int mi = 0; mi < MT; mi++) {
            const __half* base = &As[(wm + mi * 16 + g) * LDA + k0 + 2 * t];
            afr[mi][0] = *(const unsigned*)(base);
            afr[mi][1] = *(const unsigned*)(base + 8 * LDA);
            afr[mi][2] = *(const unsigned*)(base + 8);
            afr[mi][3] = *(const unsigned*)(base + 8 * LDA + 8);
        }
#pragma unroll
        for (int ni = 0; ni < 4; ni++) {
            const __half* bb = &Bs[(wn + ni * 8 + g) * LDA + k0 + 2 * t];
            bfr[ni][0] = *(const unsigned*)(bb);
            bfr[ni][1] = *(const unsigned*)(bb + 8);
        }
#pragma unroll
        for (int mi = 0; mi < MT; mi++)
#pragma unroll
            for (int ni = 0; ni < 4; ni++)
                mma16816(acc[mi][ni], afr[mi], bfr[ni]);
    }

    // epilogue: scale each row by dinv[row], store fp16
#pragma unroll
    for (int mi = 0; mi < MT; mi++) {
        int r0 = rowBase + wm + mi * 16 + g;
        float s0 = (r0 < M) ? g_dinv[r0] : 0.f;
        float s1 = (r0 + 8 < M) ? g_dinv[r0 + 8] : 0.f;
#pragma unroll
        for (int ni = 0; ni < 4; ni++) {
            int c = wn + ni * 8 + 2 * t;
            if (r0 < M) {
                __half2 h = __floats2half2_rn(acc[mi][ni][0] * s0, acc[mi][ni][1] * s0);
                *(__half2*)&g_h16[r0 * ldc + c] = h;
            }
            if (r0 + 8 < M) {
                __half2 h = __floats2half2_rn(acc[mi][ni][2] * s1, acc[mi][ni][3] * s1);
                *(__half2*)&g_h16[(r0 + 8) * ldc + c] = h;
            }
        }
    }
}

// ---------------- aggregation (F=128), warp/node, pure row sum --------------
__device__ __forceinline__ void cvt8(uint4 r, float* f) {
    __half2* p = (__half2*)&r;
    float2 a = __half22float2(p[0]);
    float2 b = __half22float2(p[1]);
    float2 c = __half22float2(p[2]);
    float2 d = __half22float2(p[3]);
    f[0] = a.x; f[1] = a.y; f[2] = b.x; f[3] = b.y;
    f[4] = c.x; f[5] = c.y; f[6] = d.x; f[7] = d.y;
}

__global__ void agg128_kernel(const float* __restrict__ bias, int n, int do_relu) {
    int gw = (blockIdx.x * blockDim.x + threadIdx.x) >> 5;
    if (gw >= n) return;
    int lane = threadIdx.x & 31;
    int hf = lane >> 4;        // which edge of each pair
    int sub = lane & 15;       // 16B chunk within the 256B row
    const uint4* __restrict__ hv = (const uint4*)g_h16;

    float acc[8];
    {   // self-loop h'[d]: each half adds 0.5x (exact after combine)
        float f[8];
        cvt8(hv[gw * 16 + sub], f);
#pragma unroll
        for (int q = 0; q < 8; q++) acc[q] = 0.5f * f[q];
    }

    int beg = g_rowptr[gw];
    int end = g_rowptr[gw + 1];
    int i = beg;
    for (; i + 7 < end; i += 8) {
        int sa = g_srcidx[i + 0 + hf];
        int sb = g_srcidx[i + 2 + hf];
        int sc = g_srcidx[i + 4 + hf];
        int sd = g_srcidx[i + 6 + hf];
        uint4 ra = hv[sa * 16 + sub];
        uint4 rb = hv[sb * 16 + sub];
        uint4 rc = hv[sc * 16 + sub];
        uint4 rd = hv[sd * 16 + sub];
        float fa[8], fb[8], fc[8], fd[8];
        cvt8(ra, fa);
        cvt8(rb, fb);
        cvt8(rc, fc);
        cvt8(rd, fd);
#pragma unroll
        for (int q = 0; q < 8; q++) acc[q] += (fa[q] + fb[q]) + (fc[q] + fd[q]);
    }
    for (; i + 1 < end; i += 2) {
        int sa = g_srcidx[i + hf];
        uint4 ra = hv[sa * 16 + sub];
        float fa[8];
        cvt8(ra, fa);
#pragma unroll
        for (int q = 0; q < 8; q++) acc[q] += fa[q];
    }
    if (i < end) {
        int s0 = g_srcidx[i];
        float w = hf ? 0.f : 1.f;
        uint4 ra = hv[s0 * 16 + sub];
        float fa[8];
        cvt8(ra, fa);
#pragma unroll
        for (int q = 0; q < 8; q++) acc[q] += w * fa[q];
    }
#pragma unroll
    for (int q = 0; q < 8; q++) acc[q] += __shfl_xor_sync(0xFFFFFFFFu, acc[q], 16);

    float dd = g_dinv[gw];
    float4 b0 = ((const float4*)bias)[sub * 2];
    float4 b1 = ((const float4*)bias)[sub * 2 + 1];
    acc[0] = acc[0] * dd + b0.x; acc[1] = acc[1] * dd + b0.y;
    acc[2] = acc[2] * dd + b0.z; acc[3] = acc[3] * dd + b0.w;
    acc[4] = acc[4] * dd + b1.x; acc[5] = acc[5] * dd + b1.y;
    acc[6] = acc[6] * dd + b1.z; acc[7] = acc[7] * dd + b1.w;
    if (do_relu) {
#pragma unroll
        for (int q = 0; q < 8; q++) acc[q] = fmaxf(acc[q], 0.f);
    }
    if (hf == 0) {
        __half2 o[4];
        o[0] = __floats2half2_rn(acc[0], acc[1]);
        o[1] = __floats2half2_rn(acc[2], acc[3]);
        o[2] = __floats2half2_rn(acc[4], acc[5]);
        o[3] = __floats2half2_rn(acc[6], acc[7]);
        *(uint4*)&g_a16[gw * 128 + sub * 8] = *(uint4*)o;
    }
}

// ---------------- layer 3 aggregation (F=40, fp16 h' stride 64) + softmax ---
__global__ void agg40_softmax_kernel(const float* __restrict__ b3,
                                     float* __restrict__ out, int n) {
    int gw = (blockIdx.x * blockDim.x + threadIdx.x) >> 5;
    if (gw >= n) return;
    int lane = threadIdx.x & 31;
    bool act = lane < 20;
    const __half2* __restrict__ hv = (const __half2*)g_h16;  // row stride = 32 half2

    float2 acc = make_float2(0.f, 0.f);
    if (act) {
        float2 v = __half22float2(hv[gw * 32 + lane]);  // self h'[d]
        acc.x = v.x;
        acc.y = v.y;
    }
    int beg = g_rowptr[gw];
    int end = g_rowptr[gw + 1];
    int i = beg;
    for (; i + 1 < end; i += 2) {
        int s0 = g_srcidx[i], s1 = g_srcidx[i + 1];
        if (act) {
            float2 v0 = __half22float2(hv[s0 * 32 + lane]);
            float2 v1 = __half22float2(hv[s1 * 32 + lane]);
            acc.x += v0.x + v1.x;
            acc.y += v0.y + v1.y;
        }
    }
    if (i < end) {
        int s = g_srcidx[i];
        if (act) {
            float2 v = __half22float2(hv[s * 32 + lane]);
            acc.x += v.x;
            acc.y += v.y;
        }
    }
    if (act) {
        float dd = g_dinv[gw];
        acc.x = acc.x * dd + b3[lane * 2];
        acc.y = acc.y * dd + b3[lane * 2 + 1];
    }
    float m = act ? fmaxf(acc.x, acc.y) : -INFINITY;
#pragma unroll
    for (int off = 16; off > 0; off >>= 1) m = fmaxf(m, __shfl_xor_sync(0xFFFFFFFFu, m, off));
    float se = act ? (expf(acc.x - m) + expf(acc.y - m)) : 0.f;
#pragma unroll
    for (int off = 16; off > 0; off >>= 1) se += __shfl_xor_sync(0xFFFFFFFFu, se, off);
    float ls = m + logf(se);
    if (act) {
        out[gw * 40 + lane * 2 + 0] = acc.x - ls;
        out[gw * 40 + lane * 2 + 1] = acc.y - ls;
    }
}

// ---------------- launch -----------------------------------------------------
extern "C" void kernel_launch(void* const* d_in, const int* in_sizes, int n_in,
                              void* d_out, int out_size) {
    const float* x = (const float*)d_in[0];
    const int* ei = (const int*)d_in[1];
    const float* W1 = (const float*)d_in[2];
    const float* b1 = (const float*)d_in[3];
    const float* W2 = (const float*)d_in[4];
    const float* b2 = (const float*)d_in[5];
    const float* W3 = (const float*)d_in[6];
    const float* b3 = (const float*)d_in[7];
    float* out = (float*)d_out;

    const int n = in_sizes[0] / 128;   // 50000
    const int ne = in_sizes[1] / 2;    // 1600000

    int eb = (ne + 255) / 256;
    int wb = (n + 7) / 8;
    int sb = (n + SCAN_TILE - 1) / SCAN_TILE;
    int gb = (n + 63) / 64;

    const int SMEM_128 = (64 + 128) * 136 * 2;  // 52224
    const int SMEM_64  = (64 + 64) * 136 * 2;   // 34816
    cudaFuncSetAttribute((const void*)gemm_hmma<128, 0, 1>,
                         cudaFuncAttributeMaxDynamicSharedMemorySize, SMEM_128);
    cudaFuncSetAttribute((const void*)gemm_hmma<128, 1, 2>,
                         cudaFuncAttributeMaxDynamicSharedMemorySize, SMEM_128);
    cudaFuncSetAttribute((const void*)gemm_hmma<64, 1, 3>,
                         cudaFuncAttributeMaxDynamicSharedMemorySize, SMEM_64);

    // g_cnt is zero at entry (zero-init on load; scan_pass3 re-zeroes each run)
    hist_kernel<<<eb, 256>>>(ei, ne);
    scan_pass1<<<sb, SCAN_TILE>>>(n);          // also computes dinv
    wt_all_kernel<<<160, 256>>>(W1, W2, W3);
    gemm_hmma<128, 0, 1><<<gb, 256, SMEM_128>>>(x, n, 128);  // profiled slot 4
    scan_pass2<<<1, SCAN_TILE>>>(sb, n);
    scan_pass3<<<sb, SCAN_TILE>>>(n);
    fill_kernel<<<eb, 256>>>(ei, ne);

    // layer 1 aggregation
    agg128_kernel<<<wb, 256>>>(b1, n, 1);
    // layer 2
    gemm_hmma<128, 1, 2><<<gb, 256, SMEM_128>>>(nullptr, n, 128);
    agg128_kernel<<<wb, 256>>>(b2, n, 1);
    // layer 3
    gemm_hmma<64, 1, 3><<<gb, 256, SMEM_64>>>(nullptr, n, 64);
    agg40_softmax_kernel<<<wb, 256>>>(b3, out, n);
}